// round 1
// baseline (speedup 1.0000x reference)
#include <cuda_runtime.h>
#include <cstdint>

// ---------------------------------------------------------------------------
// LocalSensitiveAttention (Tacotron2-style) on GB300 sm_103a
// B=64, T=2048, DEC=1024, ENC=512, ATT=128, LOC=32, K=31
//
// Pipeline:
//  1) q_kernel:      q[b,a] = query[b,:] . Q_w[a,:] + Q_b[a]
//  2) weff_kernel:   Weff[a,k] = sum_c loc_proj_w[a,c] * conv_w[c,0,k]
//                    (conv+proj collapse: loc term becomes a 128-ch conv K=31)
//  3) main_kernel:   energies[b,t] = sum_a v_w[a]*tanh(q[b,a]
//                                     + values[b,t,:].V_w[a,:]
//                                     + sum_k Weff[a,k]*caw[b,t-15+k])
//     fused fp32 GEMM (M=128 a, N=2048 t, K=512 e, batched over b)
//     using packed fma.rn.f32x2 for 2x fp32 throughput.
//  4) softmax_kernel: per-b masked softmax over T -> attention_weights
//  5) ctx_partial + ctx_reduce: context[b,e] = sum_t w[b,t]*values[b,t,e]
//     (split over 16 t-chunks for parallelism, deterministic tree reduce)
// ---------------------------------------------------------------------------

#define B_    64
#define T_    2048
#define DEC_  1024
#define ENC_  512
#define ATT_  128
#define LOC_  32
#define KW_   31

// scratch (device globals: allocation-free per harness rules)
__device__ float g_q[B_ * ATT_];
__device__ float g_weff[ATT_ * KW_];
__device__ float g_energies[B_ * T_];
__device__ float g_ctx_part[B_ * 16 * ENC_];

// packed fp32x2 FMA (sm_103a): d = a*b + d, lanewise on two packed f32
#define FMA2(d, a, b) \
    asm volatile("fma.rn.f32x2 %0, %1, %2, %0;" : "+l"(d) : "l"(a), "l"(b))

// ---------------------------------------------------------------------------
// 1) q = query @ Q_w^T + Q_b   (grid: B, 256 threads, warp-cooperative dots)
// ---------------------------------------------------------------------------
__global__ void q_kernel(const float* __restrict__ query,
                         const float* __restrict__ Qw,
                         const float* __restrict__ Qb) {
    int b = blockIdx.x;
    int wid = threadIdx.x >> 5, lane = threadIdx.x & 31;
    #pragma unroll 1
    for (int ai = 0; ai < 16; ai++) {
        int a = wid * 16 + ai;
        float s = 0.f;
        #pragma unroll 8
        for (int k = lane; k < DEC_; k += 32)
            s += query[b * DEC_ + k] * Qw[a * DEC_ + k];
        #pragma unroll
        for (int o = 16; o > 0; o >>= 1)
            s += __shfl_down_sync(0xffffffffu, s, o);
        if (lane == 0) g_q[b * ATT_ + a] = s + Qb[a];
    }
}

// ---------------------------------------------------------------------------
// 2) Weff[a,k] = sum_c loc_proj_w[a,c] * conv_w[c,0,k]  (1 block, 128 threads)
// ---------------------------------------------------------------------------
__global__ void weff_kernel(const float* __restrict__ lp,
                            const float* __restrict__ cw) {
    int a = threadIdx.x;  // 0..127
    for (int k = 0; k < KW_; k++) {
        float s = 0.f;
        #pragma unroll
        for (int c = 0; c < LOC_; c++)
            s += lp[a * LOC_ + c] * cw[c * KW_ + k];
        g_weff[a * KW_ + k] = s;
    }
}

// ---------------------------------------------------------------------------
// 3) main fused energies kernel
//    block: 256 threads, tile = 128 a x 64 t, K-chunks of 32
//    thread: tx = tid&15 owns 8 a's (4 packed pairs), ty = tid>>4 owns 4 t's
// ---------------------------------------------------------------------------
#define KC    32
#define TS_T  64
#define LDV   132   // padded smem row stride (floats) for Vw tile rows [k][a]
#define LDB   132   // vals tile rows [k][2*t duplicated]

__global__ __launch_bounds__(256, 2)
void main_kernel(const float* __restrict__ values,
                 const float* __restrict__ Vw,
                 const float* __restrict__ caw,
                 const float* __restrict__ vw_vec) {
    extern __shared__ __align__(16) float smem[];
    float* Vw_s    = smem;                      // KC*LDV = 4224
    float* vals2_s = Vw_s + KC * LDV;           // KC*LDB = 4224
    float* weff_s  = vals2_s + KC * LDB;        // 3968
    float* q_s     = weff_s + ATT_ * KW_;       // 128
    float* vwv_s   = q_s + ATT_;                // 128
    float* caw_s   = vwv_s + ATT_;              // 96 (94 used)
    float* part_s  = caw_s + 96;                // 16*65 = 1040

    const int tid = threadIdx.x;
    const int b = blockIdx.y;
    const int t0 = blockIdx.x * TS_T;
    const int tx = tid & 15;   // a-group: a in [tx*8, tx*8+8)
    const int ty = tid >> 4;   // t-group: t in [ty*4, ty*4+4)

    // preload constants
    for (int i = tid; i < ATT_ * KW_; i += 256) weff_s[i] = g_weff[i];
    if (tid < ATT_) {
        q_s[tid]   = g_q[b * ATT_ + tid];
        vwv_s[tid] = vw_vec[tid];
    }
    for (int i = tid; i < TS_T + 30; i += 256) {
        int gt = t0 - 15 + i;
        caw_s[i] = (gt >= 0 && gt < T_) ? caw[b * T_ + gt] : 0.f;
    }

    unsigned long long acc[4][4];
    #pragma unroll
    for (int i = 0; i < 4; i++)
        #pragma unroll
        for (int j = 0; j < 4; j++) acc[i][j] = 0ull;

    const float* vbase = values + (size_t)(b * T_ + t0) * ENC_;

    for (int kc = 0; kc < ENC_; kc += KC) {
        __syncthreads();
        // load V_w tile: 128a x 32k -> Vw_s[k][a] (transposed, padded)
        #pragma unroll
        for (int i = 0; i < 4; i++) {
            int idx4 = tid + i * 256;
            int a = idx4 >> 3, kq = (idx4 & 7) * 4;
            float4 g = *(const float4*)(Vw + a * ENC_ + kc + kq);
            Vw_s[(kq + 0) * LDV + a] = g.x;
            Vw_s[(kq + 1) * LDV + a] = g.y;
            Vw_s[(kq + 2) * LDV + a] = g.z;
            Vw_s[(kq + 3) * LDV + a] = g.w;
        }
        // load values tile: 64t x 32k, duplicated pairs for f32x2 operand
        #pragma unroll
        for (int i = 0; i < 2; i++) {
            int idx4 = tid + i * 256;
            int t = idx4 >> 3, kq = (idx4 & 7) * 4;
            float4 g = *(const float4*)(vbase + (size_t)t * ENC_ + kc + kq);
            *(float2*)&vals2_s[(kq + 0) * LDB + 2 * t] = make_float2(g.x, g.x);
            *(float2*)&vals2_s[(kq + 1) * LDB + 2 * t] = make_float2(g.y, g.y);
            *(float2*)&vals2_s[(kq + 2) * LDB + 2 * t] = make_float2(g.z, g.z);
            *(float2*)&vals2_s[(kq + 3) * LDB + 2 * t] = make_float2(g.w, g.w);
        }
        __syncthreads();
        #pragma unroll
        for (int k = 0; k < KC; k++) {
            // 8 a-values as 4 packed pairs (free reinterpret of float4 regs)
            ulonglong2 A01 = *(const ulonglong2*)&Vw_s[k * LDV + tx * 8];
            ulonglong2 A23 = *(const ulonglong2*)&Vw_s[k * LDV + tx * 8 + 4];
            unsigned long long Ap0 = A01.x, Ap1 = A01.y, Ap2 = A23.x, Ap3 = A23.y;
            unsigned long long Bv[4];
            #pragma unroll
            for (int j = 0; j < 4; j++)
                Bv[j] = *(const unsigned long long*)
                            &vals2_s[k * LDB + (ty * 4 + j) * 2];
            #pragma unroll
            for (int j = 0; j < 4; j++) {
                FMA2(acc[0][j], Ap0, Bv[j]);
                FMA2(acc[1][j], Ap1, Bv[j]);
                FMA2(acc[2][j], Ap2, Bv[j]);
                FMA2(acc[3][j], Ap3, Bv[j]);
            }
        }
    }

    // epilogue: add q + loc, tanh, weight by v_w, reduce over a
    float pj[4] = {0.f, 0.f, 0.f, 0.f};
    #pragma unroll
    for (int i = 0; i < 4; i++) {
        int a0 = tx * 8 + 2 * i;
        float qa0 = q_s[a0], qa1 = q_s[a0 + 1];
        float va0 = vwv_s[a0], va1 = vwv_s[a0 + 1];
        #pragma unroll
        for (int j = 0; j < 4; j++) {
            int t = ty * 4 + j;
            float lo = __uint_as_float((unsigned)(acc[i][j] & 0xffffffffull));
            float hi = __uint_as_float((unsigned)(acc[i][j] >> 32));
            float loc0 = 0.f, loc1 = 0.f;
            #pragma unroll
            for (int kk = 0; kk < KW_; kk++) {
                float c = caw_s[t + kk];
                loc0 += weff_s[a0 * KW_ + kk] * c;
                loc1 += weff_s[(a0 + 1) * KW_ + kk] * c;
            }
            pj[j] += va0 * tanhf(lo + qa0 + loc0)
                   + va1 * tanhf(hi + qa1 + loc1);
        }
    }
    __syncthreads();
    #pragma unroll
    for (int j = 0; j < 4; j++)
        part_s[tx * (TS_T + 1) + ty * 4 + j] = pj[j];
    __syncthreads();
    if (tid < TS_T) {
        float e = 0.f;
        #pragma unroll
        for (int g = 0; g < 16; g++) e += part_s[g * (TS_T + 1) + tid];
        g_energies[b * T_ + t0 + tid] = e;
    }
}

// ---------------------------------------------------------------------------
// 4) masked softmax over T, per b (deterministic tree reductions)
// ---------------------------------------------------------------------------
__global__ void softmax_kernel(const unsigned char* __restrict__ maskb,
                               float* __restrict__ out_w) {
    __shared__ float red[256];
    int b = blockIdx.x, tid = threadIdx.x;
    float e[8];
    float mx = -3.402823466e38f;
    #pragma unroll
    for (int i = 0; i < 8; i++) {
        int t = tid + i * 256;
        float v = g_energies[b * T_ + t];
        if (maskb[b * T_ + t]) v = __int_as_float(0xff800000);  // -inf
        e[i] = v;
        mx = fmaxf(mx, v);
    }
    red[tid] = mx;
    __syncthreads();
    for (int s = 128; s > 0; s >>= 1) {
        if (tid < s) red[tid] = fmaxf(red[tid], red[tid + s]);
        __syncthreads();
    }
    mx = red[0];
    __syncthreads();
    float sum = 0.f;
    #pragma unroll
    for (int i = 0; i < 8; i++) {
        e[i] = expf(e[i] - mx);
        sum += e[i];
    }
    red[tid] = sum;
    __syncthreads();
    for (int s = 128; s > 0; s >>= 1) {
        if (tid < s) red[tid] += red[tid + s];
        __syncthreads();
    }
    float inv = 1.f / red[0];
    #pragma unroll
    for (int i = 0; i < 8; i++)
        out_w[b * T_ + tid + i * 256] = e[i] * inv;
}

// ---------------------------------------------------------------------------
// 5) context = weights @ values (split over 16 t-chunks, then reduce)
// ---------------------------------------------------------------------------
__global__ void ctx_partial(const float* __restrict__ values,
                            const float* __restrict__ w) {
    int b = blockIdx.y, ch = blockIdx.x, tid = threadIdx.x;  // 256 threads
    int tstart = ch * (T_ / 16);
    float acc0 = 0.f, acc1 = 0.f;
    #pragma unroll 4
    for (int t = 0; t < T_ / 16; t++) {
        float wt = w[b * T_ + tstart + t];
        const float* vrow = values + (size_t)(b * T_ + tstart + t) * ENC_;
        acc0 += wt * vrow[tid];
        acc1 += wt * vrow[tid + 256];
    }
    g_ctx_part[(size_t)(b * 16 + ch) * ENC_ + tid] = acc0;
    g_ctx_part[(size_t)(b * 16 + ch) * ENC_ + tid + 256] = acc1;
}

__global__ void ctx_reduce(float* __restrict__ out_ctx) {
    int idx = blockIdx.x * 256 + threadIdx.x;  // B*ENC = 32768
    int b = idx >> 9, c = idx & 511;
    float s = 0.f;
    #pragma unroll
    for (int ch = 0; ch < 16; ch++)
        s += g_ctx_part[(size_t)(b * 16 + ch) * ENC_ + c];
    out_ctx[idx] = s;
}

// ---------------------------------------------------------------------------
extern "C" void kernel_launch(void* const* d_in, const int* in_sizes, int n_in,
                              void* d_out, int out_size) {
    const float* query = (const float*)d_in[0];
    const float* values = (const float*)d_in[1];
    const float* caw   = (const float*)d_in[2];
    const unsigned char* mask = (const unsigned char*)d_in[3];
    const float* Qw    = (const float*)d_in[4];
    const float* Qb    = (const float*)d_in[5];
    const float* Vw    = (const float*)d_in[6];
    const float* convw = (const float*)d_in[7];
    const float* locp  = (const float*)d_in[8];
    const float* vw    = (const float*)d_in[9];

    float* out_ctx = (float*)d_out;              // [B, ENC]
    float* out_w   = (float*)d_out + B_ * ENC_;  // [B, T]

    static const int SMEM_MAIN =
        (KC * LDV + KC * LDB + ATT_ * KW_ + ATT_ + ATT_ + 96 + 16 * 65) * 4;
    cudaFuncSetAttribute(main_kernel,
                         cudaFuncAttributeMaxDynamicSharedMemorySize, SMEM_MAIN);

    q_kernel<<<B_, 256>>>(query, Qw, Qb);
    weff_kernel<<<1, ATT_>>>(locp, convw);
    main_kernel<<<dim3(T_ / TS_T, B_), 256, SMEM_MAIN>>>(values, Vw, caw, vw);
    softmax_kernel<<<B_, 256>>>(mask, out_w);
    ctx_partial<<<dim3(16, B_), 256>>>(values, out_w);
    ctx_reduce<<<(B_ * ENC_) / 256, 256>>>(out_ctx);
}

// round 3
// speedup vs baseline: 2.8298x; 2.8298x over previous
#include <cuda_runtime.h>
#include <cuda_bf16.h>
#include <cstdint>

// ---------------------------------------------------------------------------
// LocalSensitiveAttention on GB300 (compiled as sm_103 baseline: legacy HMMA)
// B=64, T=2048, DEC=1024, ENC=512, ATT=128, LOC=32, K=31
//
// energies[b,t] = sum_a vw[a]*tanh( S[a,t] + q[b,a] ),
// S = Vw @ values^T + Weff @ cawband^T   via bf16 hi/lo split mma.sync:
//   S ~= Ahi*Bhi + Alo*Bhi + Ahi*Blo   (fp32 accum)
// ---------------------------------------------------------------------------

#define B_    64
#define T_    2048
#define DEC_  1024
#define ENC_  512
#define ATT_  128
#define LOC_  32
#define KW_   31

// device scratch
__device__ float g_q[B_ * ATT_];
__device__ float g_weff[ATT_ * KW_];
__device__ float g_energies[B_ * T_];
__device__ float g_ctx_part[B_ * 16 * ENC_];
__device__ __align__(16) uint32_t g_Ahi[ATT_ * 256];  // Vw hi bf16 pairs [a][256]
__device__ __align__(16) uint32_t g_Alo[ATT_ * 256];
__device__ __align__(16) uint32_t g_Lhi[ATT_ * 16];   // Weff (pad k32) [a][16]
__device__ __align__(16) uint32_t g_Llo[ATT_ * 16];

// ----------------------------- helpers -------------------------------------
__device__ __forceinline__ uint32_t smem_u32(const void* p) {
    uint32_t a;
    asm("{ .reg .u64 t; cvta.to.shared.u64 t, %1; cvt.u32.u64 %0, t; }"
        : "=r"(a) : "l"(p));
    return a;
}
#define CP_ASYNC16(dst, src) \
    asm volatile("cp.async.cg.shared.global [%0], [%1], 16;" :: "r"(dst), "l"(src))
#define CP_COMMIT() asm volatile("cp.async.commit_group;" ::: "memory")
#define CP_WAIT0()  asm volatile("cp.async.wait_group 0;" ::: "memory")

__device__ __forceinline__ void ldsm4(uint32_t* r, uint32_t addr) {
    asm volatile("ldmatrix.sync.aligned.m8n8.x4.shared.b16 {%0,%1,%2,%3}, [%4];"
                 : "=r"(r[0]), "=r"(r[1]), "=r"(r[2]), "=r"(r[3]) : "r"(addr));
}
__device__ __forceinline__ void hmma(float* c, const uint32_t* a,
                                     const uint32_t* b) {
    asm volatile(
        "mma.sync.aligned.m16n8k16.row.col.f32.bf16.bf16.f32 "
        "{%0,%1,%2,%3},{%4,%5,%6,%7},{%8,%9},{%0,%1,%2,%3};"
        : "+f"(c[0]), "+f"(c[1]), "+f"(c[2]), "+f"(c[3])
        : "r"(a[0]), "r"(a[1]), "r"(a[2]), "r"(a[3]), "r"(b[0]), "r"(b[1]));
}
__device__ __forceinline__ uint32_t pack_bf16x2(float a, float b) {
    __nv_bfloat162 t;
    t.x = __float2bfloat16_rn(a);
    t.y = __float2bfloat16_rn(b);
    return *reinterpret_cast<uint32_t*>(&t);
}
__device__ __forceinline__ void split_pack(float a, float b,
                                           uint32_t& hi, uint32_t& lo) {
    __nv_bfloat16 ha = __float2bfloat16_rn(a), hb = __float2bfloat16_rn(b);
    float ra = a - __bfloat162float(ha), rb = b - __bfloat162float(hb);
    __nv_bfloat162 th; th.x = ha; th.y = hb;
    hi = *reinterpret_cast<uint32_t*>(&th);
    lo = pack_bf16x2(ra, rb);
}
// accurate-enough tanh via ex2/rcp approx (err ~1e-6)
__device__ __forceinline__ float tanh_acc(float x) {
    x = fminf(fmaxf(x, -15.f), 15.f);
    float t, r;
    asm("ex2.approx.f32 %0, %1;" : "=f"(t) : "f"(x * 2.8853900817779268f));
    asm("rcp.approx.f32 %0, %1;" : "=f"(r) : "f"(t + 1.f));
    return (t - 1.f) * r;
}

// ---------------------------------------------------------------------------
// q = query @ Q_w^T + Q_b
// ---------------------------------------------------------------------------
__global__ void q_kernel(const float* __restrict__ query,
                         const float* __restrict__ Qw,
                         const float* __restrict__ Qb) {
    int b = blockIdx.x;
    int wid = threadIdx.x >> 5, lane = threadIdx.x & 31;
    #pragma unroll 1
    for (int ai = 0; ai < 16; ai++) {
        int a = wid * 16 + ai;
        float s = 0.f;
        #pragma unroll 8
        for (int k = lane; k < DEC_; k += 32)
            s += query[b * DEC_ + k] * Qw[a * DEC_ + k];
        #pragma unroll
        for (int o = 16; o > 0; o >>= 1)
            s += __shfl_down_sync(0xffffffffu, s, o);
        if (lane == 0) g_q[b * ATT_ + a] = s + Qb[a];
    }
}

// ---------------------------------------------------------------------------
// Weff[a,k] = sum_c loc_proj_w[a,c] * conv_w[c,0,k]
// ---------------------------------------------------------------------------
__global__ void weff_kernel(const float* __restrict__ lp,
                            const float* __restrict__ cw) {
    int a = threadIdx.x;
    for (int k = 0; k < KW_; k++) {
        float s = 0.f;
        #pragma unroll
        for (int c = 0; c < LOC_; c++)
            s += lp[a * LOC_ + c] * cw[c * KW_ + k];
        g_weff[a * KW_ + k] = s;
    }
}

// ---------------------------------------------------------------------------
// prepack Vw and Weff to bf16 hi/lo global images (k-major rows)
// ---------------------------------------------------------------------------
__global__ void pack_A_kernel(const float* __restrict__ Vw) {
    int a = blockIdx.x, tid = threadIdx.x;  // 128 blocks x 256 threads
    float f0 = Vw[a * ENC_ + 2 * tid], f1 = Vw[a * ENC_ + 2 * tid + 1];
    uint32_t hi, lo;
    split_pack(f0, f1, hi, lo);
    g_Ahi[a * 256 + tid] = hi;
    g_Alo[a * 256 + tid] = lo;
}
__global__ void pack_L_kernel() {
    #pragma unroll 1
    for (int i = 0; i < 8; i++) {
        int idx = threadIdx.x + i * 256;  // 2048 = 128*16
        int a = idx >> 4, p = idx & 15;
        int k0 = 2 * p, k1 = k0 + 1;
        float f0 = (k0 < KW_) ? g_weff[a * KW_ + k0] : 0.f;
        float f1 = (k1 < KW_) ? g_weff[a * KW_ + k1] : 0.f;
        uint32_t hi, lo;
        split_pack(f0, f1, hi, lo);
        g_Lhi[idx] = hi;
        g_Llo[idx] = lo;
    }
}

// ---------------------------------------------------------------------------
// main energies kernel: 256 threads, tile 128a x 128t, 17 k-chunks of 32
// ---------------------------------------------------------------------------
#define LDR    80        // smem row stride bytes (40 bf16)
#define A_TILE 10240     // 128 rows * 80B
#define OFF_A  0                         // 2 buf x 2 sel x A_TILE = 40960
#define OFF_B  40960                     // 2 sel x A_TILE = 20480
#define OFF_CAW 61440                    // 160 floats
#define OFF_Q   62144                    // 128 floats
#define OFF_VWV 62656                    // 128 floats
#define OFF_RED 63168                    // 256 floats
#define SMEM_MAIN (OFF_RED + 1024)

__device__ __forceinline__ void load_A_async(uint32_t dstbase, int c, int tid) {
    const uint32_t* srcHi;
    const uint32_t* srcLo;
    int rs;
    if (c < 16) { srcHi = g_Ahi + c * 16; srcLo = g_Alo + c * 16; rs = 256; }
    else        { srcHi = g_Lhi;          srcLo = g_Llo;          rs = 16;  }
    #pragma unroll
    for (int i = 0; i < 4; i++) {
        int idx = tid + i * 256;          // 0..1023
        int sel = idx >> 9;
        int g = idx & 511;
        int row = g >> 2, seg = g & 3;
        const uint32_t* src = (sel ? srcLo : srcHi) + row * rs + seg * 4;
        uint32_t dst = dstbase + sel * A_TILE + row * LDR + seg * 16;
        CP_ASYNC16(dst, src);
    }
}

__device__ __forceinline__ void load_B_regs(const float* __restrict__ vb,
                                            const float* __restrict__ caw_s,
                                            int c, int tid, float4* v) {
    if (c < 16) {
        #pragma unroll
        for (int j = 0; j < 4; j++) {
            int idx = tid + j * 256;
            int row = idx >> 3, col4 = idx & 7;
            v[j] = *(const float4*)(vb + (size_t)row * ENC_ + c * 32 + col4 * 4);
        }
    } else {
        #pragma unroll
        for (int j = 0; j < 4; j++) {
            int idx = tid + j * 256;
            int row = idx >> 3, col4 = idx & 7;
            int k0 = col4 * 4;
            v[j].x = (k0 + 0 < KW_) ? caw_s[row + k0 + 0] : 0.f;
            v[j].y = (k0 + 1 < KW_) ? caw_s[row + k0 + 1] : 0.f;
            v[j].z = (k0 + 2 < KW_) ? caw_s[row + k0 + 2] : 0.f;
            v[j].w = (k0 + 3 < KW_) ? caw_s[row + k0 + 3] : 0.f;
        }
    }
}

__device__ __forceinline__ void store_B(char* smem, int tid, const float4* v) {
    #pragma unroll
    for (int j = 0; j < 4; j++) {
        int idx = tid + j * 256;
        int row = idx >> 3, col4 = idx & 7;
        uint32_t h0, l0, h1, l1;
        split_pack(v[j].x, v[j].y, h0, l0);
        split_pack(v[j].z, v[j].w, h1, l1);
        char* p = smem + OFF_B + row * LDR + col4 * 8;
        *(uint2*)p = make_uint2(h0, h1);
        *(uint2*)(p + A_TILE) = make_uint2(l0, l1);
    }
}

__device__ __forceinline__ void compute_chunk(float (&acc)[4][4][4], uint32_t sb,
                                              int buf, int wm, int wn, int lane) {
    const uint32_t smA = sb + OFF_A + buf * 2 * A_TILE;
    const uint32_t smB = sb + OFF_B;
    #pragma unroll
    for (int k16 = 0; k16 < 2; k16++) {
        const int colb = k16 * 32;
        uint32_t ahi[4][4], alo[4][4];
        #pragma unroll
        for (int mt = 0; mt < 4; mt++) {
            uint32_t ad = smA + (wm + mt * 16 + (lane & 15)) * LDR + colb +
                          ((lane >> 4) << 4);
            ldsm4(ahi[mt], ad);
            ldsm4(alo[mt], ad + A_TILE);
        }
        uint32_t bhi[2][4], blo[2][4];
        #pragma unroll
        for (int np = 0; np < 2; np++) {
            int grp = lane >> 3;
            uint32_t bd = smB + (wn + np * 16 + (grp >> 1) * 8 + (lane & 7)) * LDR +
                          colb + ((grp & 1) << 4);
            ldsm4(bhi[np], bd);
            ldsm4(blo[np], bd + A_TILE);
        }
        #pragma unroll
        for (int mt = 0; mt < 4; mt++)
            #pragma unroll
            for (int nt = 0; nt < 4; nt++) {
                const uint32_t* bh = &bhi[nt >> 1][(nt & 1) * 2];
                const uint32_t* bl = &blo[nt >> 1][(nt & 1) * 2];
                hmma(acc[mt][nt], ahi[mt], bh);
                hmma(acc[mt][nt], alo[mt], bh);
                hmma(acc[mt][nt], ahi[mt], bl);
            }
    }
}

__global__ __launch_bounds__(256)
void main_mma(const float* __restrict__ values,
              const float* __restrict__ caw,
              const float* __restrict__ vw_vec) {
    extern __shared__ __align__(16) char smem[];
    const uint32_t sb = smem_u32(smem);
    const int tid = threadIdx.x, wid = tid >> 5, lane = tid & 31;
    const int b = blockIdx.y, t0 = blockIdx.x * 128;
    const int wm = (wid & 1) * 64, wn = (wid >> 1) * 32;

    float* caw_s = (float*)(smem + OFF_CAW);
    float* q_s   = (float*)(smem + OFF_Q);
    float* vwv_s = (float*)(smem + OFF_VWV);
    float* red_s = (float*)(smem + OFF_RED);

    if (tid < 160) {
        int gt = t0 - 15 + tid;
        caw_s[tid] = (gt >= 0 && gt < T_) ? caw[b * T_ + gt] : 0.f;
    }
    if (tid < ATT_) {
        q_s[tid]   = g_q[b * ATT_ + tid];
        vwv_s[tid] = vw_vec[tid];
    }
    __syncthreads();

    const float* vb = values + (size_t)(b * T_ + t0) * ENC_;
    float acc[4][4][4];
    #pragma unroll
    for (int i = 0; i < 4; i++)
        #pragma unroll
        for (int j = 0; j < 4; j++)
            #pragma unroll
            for (int e = 0; e < 4; e++) acc[i][j][e] = 0.f;

    float4 v[4];
    // prologue: chunk 0
    load_A_async(sb + OFF_A, 0, tid);
    CP_COMMIT();
    load_B_regs(vb, caw_s, 0, tid, v);
    CP_WAIT0();
    store_B(smem, tid, v);
    __syncthreads();

    #pragma unroll 1
    for (int c = 0; c < 17; c++) {
        const int nb = c + 1;
        if (nb < 17) {
            load_A_async(sb + OFF_A + (nb & 1) * 2 * A_TILE, nb, tid);
            CP_COMMIT();
            load_B_regs(vb, caw_s, nb, tid, v);
        }
        compute_chunk(acc, sb, c & 1, wm, wn, lane);
        if (nb < 17) {
            CP_WAIT0();
            __syncthreads();
            store_B(smem, tid, v);
            __syncthreads();
        }
    }

    // epilogue: tanh + weighted reduce over a
    float part[4][2];
    #pragma unroll
    for (int nt = 0; nt < 4; nt++) { part[nt][0] = 0.f; part[nt][1] = 0.f; }
    const int r0 = lane >> 2;
    #pragma unroll
    for (int mt = 0; mt < 4; mt++) {
        #pragma unroll
        for (int half = 0; half < 2; half++) {
            int a = wm + mt * 16 + r0 + half * 8;
            float qa = q_s[a], va = vwv_s[a];
            #pragma unroll
            for (int nt = 0; nt < 4; nt++) {
                #pragma unroll
                for (int p = 0; p < 2; p++) {
                    float x = acc[mt][nt][half * 2 + p] + qa;
                    part[nt][p] += va * tanh_acc(x);
                }
            }
        }
    }
    #pragma unroll
    for (int off = 4; off < 32; off <<= 1)
        #pragma unroll
        for (int nt = 0; nt < 4; nt++) {
            part[nt][0] += __shfl_xor_sync(0xffffffffu, part[nt][0], off);
            part[nt][1] += __shfl_xor_sync(0xffffffffu, part[nt][1], off);
        }
    if (lane < 4) {
        #pragma unroll
        for (int nt = 0; nt < 4; nt++) {
            red_s[(wid & 1) * 128 + wn + nt * 8 + lane * 2 + 0] = part[nt][0];
            red_s[(wid & 1) * 128 + wn + nt * 8 + lane * 2 + 1] = part[nt][1];
        }
    }
    __syncthreads();
    if (tid < 128)
        g_energies[b * T_ + t0 + tid] = red_s[tid] + red_s[128 + tid];
}

// ---------------------------------------------------------------------------
// masked softmax over T per b
// ---------------------------------------------------------------------------
__global__ void softmax_kernel(const unsigned char* __restrict__ maskb,
                               float* __restrict__ out_w) {
    __shared__ float red[256];
    int b = blockIdx.x, tid = threadIdx.x;
    float e[8];
    float mx = -3.402823466e38f;
    #pragma unroll
    for (int i = 0; i < 8; i++) {
        int t = tid + i * 256;
        float v = g_energies[b * T_ + t];
        if (maskb[b * T_ + t]) v = __int_as_float(0xff800000);
        e[i] = v;
        mx = fmaxf(mx, v);
    }
    red[tid] = mx;
    __syncthreads();
    for (int s = 128; s > 0; s >>= 1) {
        if (tid < s) red[tid] = fmaxf(red[tid], red[tid + s]);
        __syncthreads();
    }
    mx = red[0];
    __syncthreads();
    float sum = 0.f;
    #pragma unroll
    for (int i = 0; i < 8; i++) {
        e[i] = expf(e[i] - mx);
        sum += e[i];
    }
    red[tid] = sum;
    __syncthreads();
    for (int s = 128; s > 0; s >>= 1) {
        if (tid < s) red[tid] += red[tid + s];
        __syncthreads();
    }
    float inv = 1.f / red[0];
    #pragma unroll
    for (int i = 0; i < 8; i++)
        out_w[b * T_ + tid + i * 256] = e[i] * inv;
}

// ---------------------------------------------------------------------------
// context = weights @ values
// ---------------------------------------------------------------------------
__global__ void ctx_partial(const float* __restrict__ values,
                            const float* __restrict__ w) {
    int b = blockIdx.y, ch = blockIdx.x, tid = threadIdx.x;
    int tstart = ch * (T_ / 16);
    float acc0 = 0.f, acc1 = 0.f;
    #pragma unroll 4
    for (int t = 0; t < T_ / 16; t++) {
        float wt = w[b * T_ + tstart + t];
        const float* vrow = values + (size_t)(b * T_ + tstart + t) * ENC_;
        acc0 += wt * vrow[tid];
        acc1 += wt * vrow[tid + 256];
    }
    g_ctx_part[(size_t)(b * 16 + ch) * ENC_ + tid] = acc0;
    g_ctx_part[(size_t)(b * 16 + ch) * ENC_ + tid + 256] = acc1;
}

__global__ void ctx_reduce(float* __restrict__ out_ctx) {
    int idx = blockIdx.x * 256 + threadIdx.x;
    int b = idx >> 9, c = idx & 511;
    float s = 0.f;
    #pragma unroll
    for (int ch = 0; ch < 16; ch++)
        s += g_ctx_part[(size_t)(b * 16 + ch) * ENC_ + c];
    out_ctx[idx] = s;
}

// ---------------------------------------------------------------------------
extern "C" void kernel_launch(void* const* d_in, const int* in_sizes, int n_in,
                              void* d_out, int out_size) {
    const float* query = (const float*)d_in[0];
    const float* values = (const float*)d_in[1];
    const float* caw   = (const float*)d_in[2];
    const unsigned char* mask = (const unsigned char*)d_in[3];
    const float* Qw    = (const float*)d_in[4];
    const float* Qb    = (const float*)d_in[5];
    const float* Vw    = (const float*)d_in[6];
    const float* convw = (const float*)d_in[7];
    const float* locp  = (const float*)d_in[8];
    const float* vw    = (const float*)d_in[9];

    float* out_ctx = (float*)d_out;              // [B, ENC]
    float* out_w   = (float*)d_out + B_ * ENC_;  // [B, T]

    cudaFuncSetAttribute(main_mma,
                         cudaFuncAttributeMaxDynamicSharedMemorySize, SMEM_MAIN);

    q_kernel<<<B_, 256>>>(query, Qw, Qb);
    weff_kernel<<<1, ATT_>>>(locp, convw);
    pack_A_kernel<<<ATT_, 256>>>(Vw);
    pack_L_kernel<<<1, 256>>>();
    main_mma<<<dim3(T_ / 128, B_), 256, SMEM_MAIN>>>(values, caw, vw);
    softmax_kernel<<<B_, 256>>>(mask, out_w);
    ctx_partial<<<dim3(16, B_), 256>>>(values, out_w);
    ctx_reduce<<<(B_ * ENC_) / 256, 256>>>(out_ctx);
}

// round 4
// speedup vs baseline: 3.1323x; 1.1069x over previous
#include <cuda_runtime.h>
#include <cuda_bf16.h>
#include <cstdint>

// ---------------------------------------------------------------------------
// LocalSensitiveAttention on GB300 (sm_103 baseline ptx: legacy HMMA mma.sync)
// energies = vw . tanh(Vw@values^T + Weff@cawband^T + q); softmax; ctx.
// bf16 hi/lo split: S ~= Ahi*Bhi + Alo*Bhi + Ahi*Blo (fp32 accum)
// This round: 512 threads, 32x32 warp tiles, A+B double buffered (1 sync/chunk)
// ---------------------------------------------------------------------------

#define B_    64
#define T_    2048
#define DEC_  1024
#define ENC_  512
#define ATT_  128
#define LOC_  32
#define KW_   31

__device__ float g_q[B_ * ATT_];
__device__ float g_energies[B_ * T_];
__device__ float g_ctx_part[B_ * 16 * ENC_];
__device__ __align__(16) uint32_t g_Ahi[ATT_ * 256];  // Vw hi bf16 pairs [a][256]
__device__ __align__(16) uint32_t g_Alo[ATT_ * 256];
__device__ __align__(16) uint32_t g_Lhi[ATT_ * 16];   // Weff (pad k32) [a][16]
__device__ __align__(16) uint32_t g_Llo[ATT_ * 16];

// ----------------------------- helpers -------------------------------------
__device__ __forceinline__ uint32_t smem_u32(const void* p) {
    uint32_t a;
    asm("{ .reg .u64 t; cvta.to.shared.u64 t, %1; cvt.u32.u64 %0, t; }"
        : "=r"(a) : "l"(p));
    return a;
}
#define CP_ASYNC16(dst, src) \
    asm volatile("cp.async.cg.shared.global [%0], [%1], 16;" :: "r"(dst), "l"(src))
#define CP_COMMIT() asm volatile("cp.async.commit_group;" ::: "memory")
#define CP_WAIT0()  asm volatile("cp.async.wait_group 0;" ::: "memory")

__device__ __forceinline__ void ldsm4(uint32_t* r, uint32_t addr) {
    asm volatile("ldmatrix.sync.aligned.m8n8.x4.shared.b16 {%0,%1,%2,%3}, [%4];"
                 : "=r"(r[0]), "=r"(r[1]), "=r"(r[2]), "=r"(r[3]) : "r"(addr));
}
__device__ __forceinline__ void hmma(float* c, const uint32_t* a,
                                     const uint32_t* b) {
    asm volatile(
        "mma.sync.aligned.m16n8k16.row.col.f32.bf16.bf16.f32 "
        "{%0,%1,%2,%3},{%4,%5,%6,%7},{%8,%9},{%0,%1,%2,%3};"
        : "+f"(c[0]), "+f"(c[1]), "+f"(c[2]), "+f"(c[3])
        : "r"(a[0]), "r"(a[1]), "r"(a[2]), "r"(a[3]), "r"(b[0]), "r"(b[1]));
}
__device__ __forceinline__ uint32_t pack_bf16x2(float a, float b) {
    __nv_bfloat162 t;
    t.x = __float2bfloat16_rn(a);
    t.y = __float2bfloat16_rn(b);
    return *reinterpret_cast<uint32_t*>(&t);
}
__device__ __forceinline__ void split_pack(float a, float b,
                                           uint32_t& hi, uint32_t& lo) {
    __nv_bfloat16 ha = __float2bfloat16_rn(a), hb = __float2bfloat16_rn(b);
    float ra = a - __bfloat162float(ha), rb = b - __bfloat162float(hb);
    __nv_bfloat162 th; th.x = ha; th.y = hb;
    hi = *reinterpret_cast<uint32_t*>(&th);
    lo = pack_bf16x2(ra, rb);
}
__device__ __forceinline__ float tanh_acc(float x) {
    x = fminf(fmaxf(x, -15.f), 15.f);
    float t, r;
    asm("ex2.approx.f32 %0, %1;" : "=f"(t) : "f"(x * 2.8853900817779268f));
    asm("rcp.approx.f32 %0, %1;" : "=f"(r) : "f"(t + 1.f));
    return (t - 1.f) * r;
}

// ---------------------------------------------------------------------------
// q = query @ Q_w^T + Q_b
// ---------------------------------------------------------------------------
__global__ void q_kernel(const float* __restrict__ query,
                         const float* __restrict__ Qw,
                         const float* __restrict__ Qb) {
    int b = blockIdx.x;
    int wid = threadIdx.x >> 5, lane = threadIdx.x & 31;
    #pragma unroll 1
    for (int ai = 0; ai < 16; ai++) {
        int a = wid * 16 + ai;
        float s = 0.f;
        #pragma unroll 8
        for (int k = lane; k < DEC_; k += 32)
            s += query[b * DEC_ + k] * Qw[a * DEC_ + k];
        #pragma unroll
        for (int o = 16; o > 0; o >>= 1)
            s += __shfl_down_sync(0xffffffffu, s, o);
        if (lane == 0) g_q[b * ATT_ + a] = s + Qb[a];
    }
}

// ---------------------------------------------------------------------------
// prepack Vw to bf16 hi/lo images
// ---------------------------------------------------------------------------
__global__ void pack_A_kernel(const float* __restrict__ Vw) {
    int a = blockIdx.x, tid = threadIdx.x;
    float f0 = Vw[a * ENC_ + 2 * tid], f1 = Vw[a * ENC_ + 2 * tid + 1];
    uint32_t hi, lo;
    split_pack(f0, f1, hi, lo);
    g_Ahi[a * 256 + tid] = hi;
    g_Alo[a * 256 + tid] = lo;
}

// Weff[a,k] = sum_c lp[a,c]*cw[c,k], fused with bf16 hi/lo pack (8 blocks)
__global__ void pack_L_kernel(const float* __restrict__ lp,
                              const float* __restrict__ cw) {
    int idx = blockIdx.x * 256 + threadIdx.x;  // 0..2047 = 128*16
    int a = idx >> 4, p = idx & 15;
    int k0 = 2 * p, k1 = k0 + 1;
    float w0 = 0.f, w1 = 0.f;
    #pragma unroll
    for (int c = 0; c < LOC_; c++) {
        float l = lp[a * LOC_ + c];
        w0 += l * cw[c * KW_ + k0];                       // k0 <= 30 always
        if (k1 < KW_) w1 += l * cw[c * KW_ + k1];
    }
    uint32_t hi, lo;
    split_pack(w0, w1, hi, lo);
    g_Lhi[idx] = hi;
    g_Llo[idx] = lo;
}

// ---------------------------------------------------------------------------
// main energies kernel: 512 threads, tile 128a x 128t, 17 k-chunks of 32
// A and B both double buffered -> single __syncthreads per chunk
// ---------------------------------------------------------------------------
#define NT     512
#define LDR    80        // smem row stride bytes (40 bf16)
#define A_TILE 10240     // 128 rows * 80B
#define OFF_A   0                        // 2 buf x 2 sel x A_TILE = 40960
#define OFF_B   40960                    // 2 buf x 2 sel x A_TILE = 40960
#define OFF_CAW 81920                    // 160 floats
#define OFF_Q   82560                    // 128 floats
#define OFF_VWV 83072                    // 128 floats
#define OFF_RED 83584                    // 512 floats
#define SMEM_MAIN (OFF_RED + 2048)

__device__ __forceinline__ void load_A_async(uint32_t dstbase, int c, int tid) {
    const uint32_t* srcHi;
    const uint32_t* srcLo;
    int rs;
    if (c < 16) { srcHi = g_Ahi + c * 16; srcLo = g_Alo + c * 16; rs = 256; }
    else        { srcHi = g_Lhi;          srcLo = g_Llo;          rs = 16;  }
    #pragma unroll
    for (int i = 0; i < 2; i++) {
        int idx = tid + i * NT;           // 0..1023
        int sel = idx >> 9;
        int g = idx & 511;
        int row = g >> 2, seg = g & 3;
        const uint32_t* src = (sel ? srcLo : srcHi) + row * rs + seg * 4;
        uint32_t dst = dstbase + sel * A_TILE + row * LDR + seg * 16;
        CP_ASYNC16(dst, src);
    }
}

__device__ __forceinline__ void load_B_regs(const float* __restrict__ vb,
                                            const float* __restrict__ caw_s,
                                            int c, int tid, float4* v) {
    if (c < 16) {
        #pragma unroll
        for (int j = 0; j < 2; j++) {
            int idx = tid + j * NT;
            int row = idx >> 3, col4 = idx & 7;
            v[j] = *(const float4*)(vb + (size_t)row * ENC_ + c * 32 + col4 * 4);
        }
    } else {
        #pragma unroll
        for (int j = 0; j < 2; j++) {
            int idx = tid + j * NT;
            int row = idx >> 3, col4 = idx & 7;
            int k0 = col4 * 4;
            v[j].x = (k0 + 0 < KW_) ? caw_s[row + k0 + 0] : 0.f;
            v[j].y = (k0 + 1 < KW_) ? caw_s[row + k0 + 1] : 0.f;
            v[j].z = (k0 + 2 < KW_) ? caw_s[row + k0 + 2] : 0.f;
            v[j].w = (k0 + 3 < KW_) ? caw_s[row + k0 + 3] : 0.f;
        }
    }
}

__device__ __forceinline__ void store_B(char* smem, uint32_t bufoff, int tid,
                                        const float4* v) {
    #pragma unroll
    for (int j = 0; j < 2; j++) {
        int idx = tid + j * NT;
        int row = idx >> 3, col4 = idx & 7;
        uint32_t h0, l0, h1, l1;
        split_pack(v[j].x, v[j].y, h0, l0);
        split_pack(v[j].z, v[j].w, h1, l1);
        char* p = smem + OFF_B + bufoff + row * LDR + col4 * 8;
        *(uint2*)p = make_uint2(h0, h1);
        *(uint2*)(p + A_TILE) = make_uint2(l0, l1);
    }
}

__device__ __forceinline__ void compute_chunk(float (&acc)[2][4][4], uint32_t sb,
                                              int buf, int wm, int wn, int lane) {
    const uint32_t smA = sb + OFF_A + buf * 2 * A_TILE;
    const uint32_t smB = sb + OFF_B + buf * 2 * A_TILE;
    #pragma unroll
    for (int k16 = 0; k16 < 2; k16++) {
        const int colb = k16 * 32;
        uint32_t ahi[2][4], alo[2][4];
        #pragma unroll
        for (int mt = 0; mt < 2; mt++) {
            uint32_t ad = smA + (wm + mt * 16 + (lane & 15)) * LDR + colb +
                          ((lane >> 4) << 4);
            ldsm4(ahi[mt], ad);
            ldsm4(alo[mt], ad + A_TILE);
        }
        uint32_t bhi[2][4], blo[2][4];
        #pragma unroll
        for (int np = 0; np < 2; np++) {
            int grp = lane >> 3;
            uint32_t bd = smB + (wn + np * 16 + (grp >> 1) * 8 + (lane & 7)) * LDR +
                          colb + ((grp & 1) << 4);
            ldsm4(bhi[np], bd);
            ldsm4(blo[np], bd + A_TILE);
        }
        #pragma unroll
        for (int mt = 0; mt < 2; mt++)
            #pragma unroll
            for (int nt = 0; nt < 4; nt++) {
                const uint32_t* bh = &bhi[nt >> 1][(nt & 1) * 2];
                const uint32_t* bl = &blo[nt >> 1][(nt & 1) * 2];
                hmma(acc[mt][nt], ahi[mt], bh);
                hmma(acc[mt][nt], alo[mt], bh);
                hmma(acc[mt][nt], ahi[mt], bl);
            }
    }
}

__global__ __launch_bounds__(NT, 1)
void main_mma(const float* __restrict__ values,
              const float* __restrict__ caw,
              const float* __restrict__ vw_vec) {
    extern __shared__ __align__(16) char smem[];
    const uint32_t sb = smem_u32(smem);
    const int tid = threadIdx.x, wid = tid >> 5, lane = tid & 31;
    const int b = blockIdx.y, t0 = blockIdx.x * 128;
    const int wm = (wid & 3) * 32, wn = (wid >> 2) * 32;

    float* caw_s = (float*)(smem + OFF_CAW);
    float* q_s   = (float*)(smem + OFF_Q);
    float* vwv_s = (float*)(smem + OFF_VWV);
    float* red_s = (float*)(smem + OFF_RED);

    if (tid < 160) {
        int gt = t0 - 15 + tid;
        caw_s[tid] = (gt >= 0 && gt < T_) ? caw[b * T_ + gt] : 0.f;
    }
    if (tid < ATT_) {
        q_s[tid]   = g_q[b * ATT_ + tid];
        vwv_s[tid] = vw_vec[tid];
    }
    __syncthreads();

    const float* vb = values + (size_t)(b * T_ + t0) * ENC_;
    float acc[2][4][4];
    #pragma unroll
    for (int i = 0; i < 2; i++)
        #pragma unroll
        for (int j = 0; j < 4; j++)
            #pragma unroll
            for (int e = 0; e < 4; e++) acc[i][j][e] = 0.f;

    float4 v[2];
    // prologue
    load_A_async(sb + OFF_A, 0, tid);
    CP_COMMIT();
    load_B_regs(vb, caw_s, 0, tid, v);
    store_B(smem, 0, tid, v);
    CP_WAIT0();
    __syncthreads();

    #pragma unroll 1
    for (int c = 0; c < 17; c++) {
        const int nb = c + 1;
        if (nb < 17) {
            load_A_async(sb + OFF_A + (nb & 1) * 2 * A_TILE, nb, tid);
            CP_COMMIT();
            load_B_regs(vb, caw_s, nb, tid, v);   // LDGs fly during compute
        }
        compute_chunk(acc, sb, c & 1, wm, wn, lane);
        if (nb < 17) {
            store_B(smem, (nb & 1) * 2 * A_TILE, tid, v);
            CP_WAIT0();
            __syncthreads();
        }
    }

    // epilogue: tanh + weighted reduce over a
    float part[4][2];
    #pragma unroll
    for (int nt = 0; nt < 4; nt++) { part[nt][0] = 0.f; part[nt][1] = 0.f; }
    const int r0 = lane >> 2;
    #pragma unroll
    for (int mt = 0; mt < 2; mt++) {
        #pragma unroll
        for (int half = 0; half < 2; half++) {
            int a = wm + mt * 16 + r0 + half * 8;
            float qa = q_s[a], va = vwv_s[a];
            #pragma unroll
            for (int nt = 0; nt < 4; nt++) {
                #pragma unroll
                for (int p = 0; p < 2; p++) {
                    float x = acc[mt][nt][half * 2 + p] + qa;
                    part[nt][p] += va * tanh_acc(x);
                }
            }
        }
    }
    #pragma unroll
    for (int off = 4; off < 32; off <<= 1)
        #pragma unroll
        for (int nt = 0; nt < 4; nt++) {
            part[nt][0] += __shfl_xor_sync(0xffffffffu, part[nt][0], off);
            part[nt][1] += __shfl_xor_sync(0xffffffffu, part[nt][1], off);
        }
    if (lane < 4) {
        #pragma unroll
        for (int nt = 0; nt < 4; nt++) {
            red_s[(wid & 3) * 128 + wn + nt * 8 + lane * 2 + 0] = part[nt][0];
            red_s[(wid & 3) * 128 + wn + nt * 8 + lane * 2 + 1] = part[nt][1];
        }
    }
    __syncthreads();
    if (tid < 128)
        g_energies[b * T_ + t0 + tid] = (red_s[tid] + red_s[128 + tid]) +
                                        (red_s[256 + tid] + red_s[384 + tid]);
}

// ---------------------------------------------------------------------------
// masked softmax over T per b
// ---------------------------------------------------------------------------
__global__ void softmax_kernel(const unsigned char* __restrict__ maskb,
                               float* __restrict__ out_w) {
    __shared__ float red[256];
    int b = blockIdx.x, tid = threadIdx.x;
    float e[8];
    float mx = -3.402823466e38f;
    #pragma unroll
    for (int i = 0; i < 8; i++) {
        int t = tid + i * 256;
        float v = g_energies[b * T_ + t];
        if (maskb[b * T_ + t]) v = __int_as_float(0xff800000);
        e[i] = v;
        mx = fmaxf(mx, v);
    }
    red[tid] = mx;
    __syncthreads();
    for (int s = 128; s > 0; s >>= 1) {
        if (tid < s) red[tid] = fmaxf(red[tid], red[tid + s]);
        __syncthreads();
    }
    mx = red[0];
    __syncthreads();
    float sum = 0.f;
    #pragma unroll
    for (int i = 0; i < 8; i++) {
        e[i] = expf(e[i] - mx);
        sum += e[i];
    }
    red[tid] = sum;
    __syncthreads();
    for (int s = 128; s > 0; s >>= 1) {
        if (tid < s) red[tid] += red[tid + s];
        __syncthreads();
    }
    float inv = 1.f / red[0];
    #pragma unroll
    for (int i = 0; i < 8; i++)
        out_w[b * T_ + tid + i * 256] = e[i] * inv;
}

// ---------------------------------------------------------------------------
// context = weights @ values
// ---------------------------------------------------------------------------
__global__ void ctx_partial(const float* __restrict__ values,
                            const float* __restrict__ w) {
    int b = blockIdx.y, ch = blockIdx.x, tid = threadIdx.x;
    int tstart = ch * (T_ / 16);
    float acc0 = 0.f, acc1 = 0.f;
    #pragma unroll 4
    for (int t = 0; t < T_ / 16; t++) {
        float wt = w[b * T_ + tstart + t];
        const float* vrow = values + (size_t)(b * T_ + tstart + t) * ENC_;
        acc0 += wt * vrow[tid];
        acc1 += wt * vrow[tid + 256];
    }
    g_ctx_part[(size_t)(b * 16 + ch) * ENC_ + tid] = acc0;
    g_ctx_part[(size_t)(b * 16 + ch) * ENC_ + tid + 256] = acc1;
}

__global__ void ctx_reduce(float* __restrict__ out_ctx) {
    int idx = blockIdx.x * 256 + threadIdx.x;
    int b = idx >> 9, c = idx & 511;
    float s = 0.f;
    #pragma unroll
    for (int ch = 0; ch < 16; ch++)
        s += g_ctx_part[(size_t)(b * 16 + ch) * ENC_ + c];
    out_ctx[idx] = s;
}

// ---------------------------------------------------------------------------
extern "C" void kernel_launch(void* const* d_in, const int* in_sizes, int n_in,
                              void* d_out, int out_size) {
    const float* query = (const float*)d_in[0];
    const float* values = (const float*)d_in[1];
    const float* caw   = (const float*)d_in[2];
    const unsigned char* mask = (const unsigned char*)d_in[3];
    const float* Qw    = (const float*)d_in[4];
    const float* Qb    = (const float*)d_in[5];
    const float* Vw    = (const float*)d_in[6];
    const float* convw = (const float*)d_in[7];
    const float* locp  = (const float*)d_in[8];
    const float* vw    = (const float*)d_in[9];

    float* out_ctx = (float*)d_out;              // [B, ENC]
    float* out_w   = (float*)d_out + B_ * ENC_;  // [B, T]

    cudaFuncSetAttribute(main_mma,
                         cudaFuncAttributeMaxDynamicSharedMemorySize, SMEM_MAIN);

    q_kernel<<<B_, 256>>>(query, Qw, Qb);
    pack_A_kernel<<<ATT_, 256>>>(Vw);
    pack_L_kernel<<<8, 256>>>(locp, convw);
    main_mma<<<dim3(T_ / 128, B_), NT, SMEM_MAIN>>>(values, caw, vw);
    softmax_kernel<<<B_, 256>>>(mask, out_w);
    ctx_partial<<<dim3(16, B_), 256>>>(values, out_w);
    ctx_reduce<<<(B_ * ENC_) / 256, 256>>>(out_ctx);
}

// round 5
// speedup vs baseline: 3.3287x; 1.0627x over previous
#include <cuda_runtime.h>
#include <cuda_bf16.h>
#include <cstdint>

// ---------------------------------------------------------------------------
// LocalSensitiveAttention on GB300 (sm_103 baseline ptx: legacy HMMA mma.sync)
// energies = vw . tanh(Vw@values^T + Weff@cawband^T + q); softmax; ctx.
// bf16 hi/lo split: S ~= Ahi*Bhi + Alo*Bhi + Ahi*Blo (fp32 accum)
// Round 5: KC=64 (9 barriers instead of 17), fused prep, float4 ctx pass.
// ---------------------------------------------------------------------------

#define B_    64
#define T_    2048
#define DEC_  1024
#define ENC_  512
#define ATT_  128
#define LOC_  32
#define KW_   31

__device__ float g_q[B_ * ATT_];
__device__ float g_energies[B_ * T_];
__device__ float g_ctx_part[B_ * 16 * ENC_];
__device__ __align__(16) uint32_t g_Ahi[ATT_ * 256];  // Vw hi bf16 pairs [a][256]
__device__ __align__(16) uint32_t g_Alo[ATT_ * 256];
__device__ __align__(16) uint32_t g_Lhi[ATT_ * 16];   // Weff (pad k32) [a][16]
__device__ __align__(16) uint32_t g_Llo[ATT_ * 16];

// ----------------------------- helpers -------------------------------------
__device__ __forceinline__ uint32_t smem_u32(const void* p) {
    uint32_t a;
    asm("{ .reg .u64 t; cvta.to.shared.u64 t, %1; cvt.u32.u64 %0, t; }"
        : "=r"(a) : "l"(p));
    return a;
}
#define CP_ASYNC16(dst, src) \
    asm volatile("cp.async.cg.shared.global [%0], [%1], 16;" :: "r"(dst), "l"(src))
#define CP_COMMIT() asm volatile("cp.async.commit_group;" ::: "memory")
#define CP_WAIT0()  asm volatile("cp.async.wait_group 0;" ::: "memory")

__device__ __forceinline__ void ldsm4(uint32_t* r, uint32_t addr) {
    asm volatile("ldmatrix.sync.aligned.m8n8.x4.shared.b16 {%0,%1,%2,%3}, [%4];"
                 : "=r"(r[0]), "=r"(r[1]), "=r"(r[2]), "=r"(r[3]) : "r"(addr));
}
__device__ __forceinline__ void hmma(float* c, const uint32_t* a,
                                     const uint32_t* b) {
    asm volatile(
        "mma.sync.aligned.m16n8k16.row.col.f32.bf16.bf16.f32 "
        "{%0,%1,%2,%3},{%4,%5,%6,%7},{%8,%9},{%0,%1,%2,%3};"
        : "+f"(c[0]), "+f"(c[1]), "+f"(c[2]), "+f"(c[3])
        : "r"(a[0]), "r"(a[1]), "r"(a[2]), "r"(a[3]), "r"(b[0]), "r"(b[1]));
}
__device__ __forceinline__ uint32_t pack_bf16x2(float a, float b) {
    __nv_bfloat162 t;
    t.x = __float2bfloat16_rn(a);
    t.y = __float2bfloat16_rn(b);
    return *reinterpret_cast<uint32_t*>(&t);
}
__device__ __forceinline__ void split_pack(float a, float b,
                                           uint32_t& hi, uint32_t& lo) {
    __nv_bfloat16 ha = __float2bfloat16_rn(a), hb = __float2bfloat16_rn(b);
    float ra = a - __bfloat162float(ha), rb = b - __bfloat162float(hb);
    __nv_bfloat162 th; th.x = ha; th.y = hb;
    hi = *reinterpret_cast<uint32_t*>(&th);
    lo = pack_bf16x2(ra, rb);
}
__device__ __forceinline__ float tanh_acc(float x) {
    x = fminf(fmaxf(x, -15.f), 15.f);
    float t, r;
    asm("ex2.approx.f32 %0, %1;" : "=f"(t) : "f"(x * 2.8853900817779268f));
    asm("rcp.approx.f32 %0, %1;" : "=f"(r) : "f"(t + 1.f));
    return (t - 1.f) * r;
}

// ---------------------------------------------------------------------------
// fused prep: blocks 0..63 q; 64..191 pack_A; 192..199 pack_L
// ---------------------------------------------------------------------------
__global__ void prep_kernel(const float* __restrict__ query,
                            const float* __restrict__ Qw,
                            const float* __restrict__ Qb,
                            const float* __restrict__ Vw,
                            const float* __restrict__ lp,
                            const float* __restrict__ cw) {
    int bid = blockIdx.x, tid = threadIdx.x;
    if (bid < 64) {                      // q = query @ Qw^T + Qb
        int b = bid, wid = tid >> 5, lane = tid & 31;
        #pragma unroll 1
        for (int ai = 0; ai < 16; ai++) {
            int a = wid * 16 + ai;
            float s = 0.f;
            #pragma unroll 8
            for (int k = lane; k < DEC_; k += 32)
                s += query[b * DEC_ + k] * Qw[a * DEC_ + k];
            #pragma unroll
            for (int o = 16; o > 0; o >>= 1)
                s += __shfl_down_sync(0xffffffffu, s, o);
            if (lane == 0) g_q[b * ATT_ + a] = s + Qb[a];
        }
    } else if (bid < 192) {              // pack Vw -> hi/lo
        int a = bid - 64;
        float f0 = Vw[a * ENC_ + 2 * tid], f1 = Vw[a * ENC_ + 2 * tid + 1];
        uint32_t hi, lo;
        split_pack(f0, f1, hi, lo);
        g_Ahi[a * 256 + tid] = hi;
        g_Alo[a * 256 + tid] = lo;
    } else {                             // Weff + pack
        int idx = (bid - 192) * 256 + tid;   // 0..2047 = 128*16
        int a = idx >> 4, p = idx & 15;
        int k0 = 2 * p, k1 = k0 + 1;
        float w0 = 0.f, w1 = 0.f;
        #pragma unroll
        for (int c = 0; c < LOC_; c++) {
            float l = lp[a * LOC_ + c];
            w0 += l * cw[c * KW_ + k0];
            if (k1 < KW_) w1 += l * cw[c * KW_ + k1];
        }
        uint32_t hi, lo;
        split_pack(w0, w1, hi, lo);
        g_Lhi[idx] = hi;
        g_Llo[idx] = lo;
    }
}

// ---------------------------------------------------------------------------
// main energies kernel: 512 threads, tile 128a x 128t
// 8 chunks of k=64 + 1 loc chunk of k=32; A+B double buffered
// ---------------------------------------------------------------------------
#define NT     512
#define LDR    144       // smem row stride bytes (64 bf16 data + 16B pad)
#define A_TILE 18432     // 128 rows * 144B
#define OFF_A   0                        // 2 buf x 2 sel x A_TILE = 73728
#define OFF_B   73728                    // 2 buf x 2 sel x A_TILE = 73728
#define OFF_CAW 147456                   // 160 floats
#define OFF_Q   148096                   // 128 floats
#define OFF_VWV 148608                   // 128 floats
#define OFF_RED 149120                   // 512 floats
#define SMEM_MAIN (OFF_RED + 2048)

// KC=64 chunk A loader (c in 0..7)
__device__ __forceinline__ void load_A_async64(uint32_t dstbase, int c, int tid) {
    #pragma unroll
    for (int i = 0; i < 4; i++) {
        int idx = tid + i * NT;           // 0..2047
        int sel = idx >> 10;
        int g = idx & 1023;
        int row = g >> 3, seg = g & 7;
        const uint32_t* src = (sel ? g_Alo : g_Ahi) + row * 256 + c * 32 + seg * 4;
        uint32_t dst = dstbase + sel * A_TILE + row * LDR + seg * 16;
        CP_ASYNC16(dst, src);
    }
}
// loc chunk (k=32) A loader
__device__ __forceinline__ void load_A_asyncL(uint32_t dstbase, int tid) {
    #pragma unroll
    for (int i = 0; i < 2; i++) {
        int idx = tid + i * NT;           // 0..1023
        int sel = idx >> 9;
        int g = idx & 511;
        int row = g >> 2, seg = g & 3;
        const uint32_t* src = (sel ? g_Llo : g_Lhi) + row * 16 + seg * 4;
        uint32_t dst = dstbase + sel * A_TILE + row * LDR + seg * 16;
        CP_ASYNC16(dst, src);
    }
}

__device__ __forceinline__ void load_B_regs64(const float* __restrict__ vb,
                                              int c, int tid, float4* v) {
    #pragma unroll
    for (int j = 0; j < 4; j++) {
        int idx = tid + j * NT;
        int row = idx >> 4, col4 = idx & 15;
        v[j] = *(const float4*)(vb + (size_t)row * ENC_ + c * 64 + col4 * 4);
    }
}
__device__ __forceinline__ void load_B_regsL(const float* __restrict__ caw_s,
                                             int tid, float4* v) {
    #pragma unroll
    for (int j = 0; j < 2; j++) {
        int idx = tid + j * NT;
        int row = idx >> 3, col4 = idx & 7;
        int k0 = col4 * 4;
        v[j].x = (k0 + 0 < KW_) ? caw_s[row + k0 + 0] : 0.f;
        v[j].y = (k0 + 1 < KW_) ? caw_s[row + k0 + 1] : 0.f;
        v[j].z = (k0 + 2 < KW_) ? caw_s[row + k0 + 2] : 0.f;
        v[j].w = (k0 + 3 < KW_) ? caw_s[row + k0 + 3] : 0.f;
    }
}

__device__ __forceinline__ void store_B64(char* smem, uint32_t bufoff, int tid,
                                          const float4* v) {
    #pragma unroll
    for (int j = 0; j < 4; j++) {
        int idx = tid + j * NT;
        int row = idx >> 4, col4 = idx & 15;
        uint32_t h0, l0, h1, l1;
        split_pack(v[j].x, v[j].y, h0, l0);
        split_pack(v[j].z, v[j].w, h1, l1);
        char* p = smem + OFF_B + bufoff + row * LDR + col4 * 8;
        *(uint2*)p = make_uint2(h0, h1);
        *(uint2*)(p + A_TILE) = make_uint2(l0, l1);
    }
}
__device__ __forceinline__ void store_BL(char* smem, uint32_t bufoff, int tid,
                                         const float4* v) {
    #pragma unroll
    for (int j = 0; j < 2; j++) {
        int idx = tid + j * NT;
        int row = idx >> 3, col4 = idx & 7;
        uint32_t h0, l0, h1, l1;
        split_pack(v[j].x, v[j].y, h0, l0);
        split_pack(v[j].z, v[j].w, h1, l1);
        char* p = smem + OFF_B + bufoff + row * LDR + col4 * 8;
        *(uint2*)p = make_uint2(h0, h1);
        *(uint2*)(p + A_TILE) = make_uint2(l0, l1);
    }
}

template <int NK16>
__device__ __forceinline__ void compute_chunk(float (&acc)[2][4][4], uint32_t sb,
                                              int buf, int wm, int wn, int lane) {
    const uint32_t smA = sb + OFF_A + buf * 2 * A_TILE;
    const uint32_t smB = sb + OFF_B + buf * 2 * A_TILE;
    #pragma unroll
    for (int k16 = 0; k16 < NK16; k16++) {
        const int colb = k16 * 32;
        uint32_t ahi[2][4], alo[2][4];
        #pragma unroll
        for (int mt = 0; mt < 2; mt++) {
            uint32_t ad = smA + (wm + mt * 16 + (lane & 15)) * LDR + colb +
                          ((lane >> 4) << 4);
            ldsm4(ahi[mt], ad);
            ldsm4(alo[mt], ad + A_TILE);
        }
        uint32_t bhi[2][4], blo[2][4];
        #pragma unroll
        for (int np = 0; np < 2; np++) {
            int grp = lane >> 3;
            uint32_t bd = smB + (wn + np * 16 + (grp >> 1) * 8 + (lane & 7)) * LDR +
                          colb + ((grp & 1) << 4);
            ldsm4(bhi[np], bd);
            ldsm4(blo[np], bd + A_TILE);
        }
        #pragma unroll
        for (int mt = 0; mt < 2; mt++)
            #pragma unroll
            for (int nt = 0; nt < 4; nt++) {
                const uint32_t* bh = &bhi[nt >> 1][(nt & 1) * 2];
                const uint32_t* bl = &blo[nt >> 1][(nt & 1) * 2];
                hmma(acc[mt][nt], ahi[mt], bh);
                hmma(acc[mt][nt], alo[mt], bh);
                hmma(acc[mt][nt], ahi[mt], bl);
            }
    }
}

__global__ __launch_bounds__(NT, 1)
void main_mma(const float* __restrict__ values,
              const float* __restrict__ caw,
              const float* __restrict__ vw_vec) {
    extern __shared__ __align__(16) char smem[];
    const uint32_t sb = smem_u32(smem);
    const int tid = threadIdx.x, wid = tid >> 5, lane = tid & 31;
    const int b = blockIdx.y, t0 = blockIdx.x * 128;
    const int wm = (wid & 3) * 32, wn = (wid >> 2) * 32;

    float* caw_s = (float*)(smem + OFF_CAW);
    float* q_s   = (float*)(smem + OFF_Q);
    float* vwv_s = (float*)(smem + OFF_VWV);
    float* red_s = (float*)(smem + OFF_RED);

    if (tid < 160) {
        int gt = t0 - 15 + tid;
        caw_s[tid] = (gt >= 0 && gt < T_) ? caw[b * T_ + gt] : 0.f;
    }
    if (tid < ATT_) {
        q_s[tid]   = g_q[b * ATT_ + tid];
        vwv_s[tid] = vw_vec[tid];
    }
    __syncthreads();

    const float* vb = values + (size_t)(b * T_ + t0) * ENC_;
    float acc[2][4][4];
    #pragma unroll
    for (int i = 0; i < 2; i++)
        #pragma unroll
        for (int j = 0; j < 4; j++)
            #pragma unroll
            for (int e = 0; e < 4; e++) acc[i][j][e] = 0.f;

    float4 v[4];
    // prologue: chunk 0
    load_A_async64(sb + OFF_A, 0, tid);
    CP_COMMIT();
    load_B_regs64(vb, 0, tid, v);
    store_B64(smem, 0, tid, v);
    CP_WAIT0();
    __syncthreads();

    #pragma unroll 1
    for (int c = 0; c < 8; c++) {
        const int nb = c + 1;
        const uint32_t nbo = (nb & 1) * 2 * A_TILE;
        if (nb < 8) {
            load_A_async64(sb + OFF_A + nbo, nb, tid);
            CP_COMMIT();
            load_B_regs64(vb, nb, tid, v);
        } else {
            load_A_asyncL(sb + OFF_A + nbo, tid);
            CP_COMMIT();
            load_B_regsL(caw_s, tid, v);
        }
        compute_chunk<4>(acc, sb, c & 1, wm, wn, lane);
        if (nb < 8) store_B64(smem, nbo, tid, v);
        else        store_BL(smem, nbo, tid, v);
        CP_WAIT0();
        __syncthreads();
    }
    compute_chunk<2>(acc, sb, 0, wm, wn, lane);   // loc chunk (buf 0, k=32)

    // epilogue: tanh + weighted reduce over a
    float part[4][2];
    #pragma unroll
    for (int nt = 0; nt < 4; nt++) { part[nt][0] = 0.f; part[nt][1] = 0.f; }
    const int r0 = lane >> 2;
    #pragma unroll
    for (int mt = 0; mt < 2; mt++) {
        #pragma unroll
        for (int half = 0; half < 2; half++) {
            int a = wm + mt * 16 + r0 + half * 8;
            float qa = q_s[a], va = vwv_s[a];
            #pragma unroll
            for (int nt = 0; nt < 4; nt++) {
                #pragma unroll
                for (int p = 0; p < 2; p++) {
                    float x = acc[mt][nt][half * 2 + p] + qa;
                    part[nt][p] += va * tanh_acc(x);
                }
            }
        }
    }
    #pragma unroll
    for (int off = 4; off < 32; off <<= 1)
        #pragma unroll
        for (int nt = 0; nt < 4; nt++) {
            part[nt][0] += __shfl_xor_sync(0xffffffffu, part[nt][0], off);
            part[nt][1] += __shfl_xor_sync(0xffffffffu, part[nt][1], off);
        }
    if (lane < 4) {
        #pragma unroll
        for (int nt = 0; nt < 4; nt++) {
            red_s[(wid & 3) * 128 + wn + nt * 8 + lane * 2 + 0] = part[nt][0];
            red_s[(wid & 3) * 128 + wn + nt * 8 + lane * 2 + 1] = part[nt][1];
        }
    }
    __syncthreads();
    if (tid < 128)
        g_energies[b * T_ + t0 + tid] = (red_s[tid] + red_s[128 + tid]) +
                                        (red_s[256 + tid] + red_s[384 + tid]);
}

// ---------------------------------------------------------------------------
// masked softmax over T per b
// ---------------------------------------------------------------------------
__global__ void softmax_kernel(const unsigned char* __restrict__ maskb,
                               float* __restrict__ out_w) {
    __shared__ float red[256];
    int b = blockIdx.x, tid = threadIdx.x;
    float e[8];
    float mx = -3.402823466e38f;
    #pragma unroll
    for (int i = 0; i < 8; i++) {
        int t = tid + i * 256;
        float v = g_energies[b * T_ + t];
        if (maskb[b * T_ + t]) v = __int_as_float(0xff800000);
        e[i] = v;
        mx = fmaxf(mx, v);
    }
    red[tid] = mx;
    __syncthreads();
    for (int s = 128; s > 0; s >>= 1) {
        if (tid < s) red[tid] = fmaxf(red[tid], red[tid + s]);
        __syncthreads();
    }
    mx = red[0];
    __syncthreads();
    float sum = 0.f;
    #pragma unroll
    for (int i = 0; i < 8; i++) {
        e[i] = expf(e[i] - mx);
        sum += e[i];
    }
    red[tid] = sum;
    __syncthreads();
    for (int s = 128; s > 0; s >>= 1) {
        if (tid < s) red[tid] += red[tid + s];
        __syncthreads();
    }
    float inv = 1.f / red[0];
    #pragma unroll
    for (int i = 0; i < 8; i++)
        out_w[b * T_ + tid + i * 256] = e[i] * inv;
}

// ---------------------------------------------------------------------------
// context = weights @ values : float4 loads, 16 t-chunks of 128, parity pairs
// ---------------------------------------------------------------------------
__global__ void ctx_partial(const float* __restrict__ values,
                            const float* __restrict__ w) {
    __shared__ float sw[128];
    __shared__ float4 sh[128];
    int b = blockIdx.y, ch = blockIdx.x, tid = threadIdx.x;  // 256 threads
    int col4 = tid & 127, parity = tid >> 7;
    const float* vb = values + (size_t)(b * T_ + ch * 128) * ENC_;
    if (tid < 128) sw[tid] = w[b * T_ + ch * 128 + tid];
    __syncthreads();
    float4 acc = make_float4(0.f, 0.f, 0.f, 0.f);
    #pragma unroll 4
    for (int r = parity; r < 128; r += 2) {
        float wt = sw[r];
        float4 vv = *(const float4*)(vb + (size_t)r * ENC_ + col4 * 4);
        acc.x += wt * vv.x;
        acc.y += wt * vv.y;
        acc.z += wt * vv.z;
        acc.w += wt * vv.w;
    }
    if (parity == 1) sh[col4] = acc;
    __syncthreads();
    if (parity == 0) {
        float4 o = sh[col4];
        o.x += acc.x; o.y += acc.y; o.z += acc.z; o.w += acc.w;
        *(float4*)(&g_ctx_part[(size_t)(b * 16 + ch) * ENC_ + col4 * 4]) = o;
    }
}

__global__ void ctx_reduce(float* __restrict__ out_ctx) {
    int idx = blockIdx.x * 256 + threadIdx.x;
    int b = idx >> 9, c = idx & 511;
    float s = 0.f;
    #pragma unroll
    for (int ch = 0; ch < 16; ch++)
        s += g_ctx_part[(size_t)(b * 16 + ch) * ENC_ + c];
    out_ctx[idx] = s;
}

// ---------------------------------------------------------------------------
extern "C" void kernel_launch(void* const* d_in, const int* in_sizes, int n_in,
                              void* d_out, int out_size) {
    const float* query = (const float*)d_in[0];
    const float* values = (const float*)d_in[1];
    const float* caw   = (const float*)d_in[2];
    const unsigned char* mask = (const unsigned char*)d_in[3];
    const float* Qw    = (const float*)d_in[4];
    const float* Qb    = (const float*)d_in[5];
    const float* Vw    = (const float*)d_in[6];
    const float* convw = (const float*)d_in[7];
    const float* locp  = (const float*)d_in[8];
    const float* vw    = (const float*)d_in[9];

    float* out_ctx = (float*)d_out;              // [B, ENC]
    float* out_w   = (float*)d_out + B_ * ENC_;  // [B, T]

    cudaFuncSetAttribute(main_mma,
                         cudaFuncAttributeMaxDynamicSharedMemorySize, SMEM_MAIN);

    prep_kernel<<<200, 256>>>(query, Qw, Qb, Vw, locp, convw);
    main_mma<<<dim3(T_ / 128, B_), NT, SMEM_MAIN>>>(values, caw, vw);
    softmax_kernel<<<B_, 256>>>(mask, out_w);
    ctx_partial<<<dim3(16, B_), 256>>>(values, out_w);
    ctx_reduce<<<(B_ * ENC_) / 256, 256>>>(out_ctx);
}

// round 7
// speedup vs baseline: 4.0004x; 1.2018x over previous
#include <cuda_runtime.h>
#include <cuda_fp16.h>
#include <cstdint>

// ---------------------------------------------------------------------------
// LocalSensitiveAttention on GB300 (sm_103 baseline ptx: legacy HMMA mma.sync)
// energies = vw . tanh(Vw@values^T + Weff@cawband^T + q); softmax; ctx.
// Round 7: fp16 numerics (fixed loc-chunk buffer index: buf 0, was 1).
// A (weights) = fp16 hi+lo (err ~2^-22), B (values) = single fp16 (err 2^-11).
// S ~= Ahi*B + Alo*B, fp32 accum. 2 GEMM combos; B smem/convert halved.
// ---------------------------------------------------------------------------

#define B_    64
#define T_    2048
#define DEC_  1024
#define ENC_  512
#define ATT_  128
#define LOC_  32
#define KW_   31

__device__ float g_q[B_ * ATT_];
__device__ float g_energies[B_ * T_];
__device__ float g_ctx_part[B_ * 16 * ENC_];
__device__ __align__(16) uint32_t g_Ahi[ATT_ * 256];  // Vw hi fp16 pairs [a][256]
__device__ __align__(16) uint32_t g_Alo[ATT_ * 256];
__device__ __align__(16) uint32_t g_Lhi[ATT_ * 16];   // Weff (pad k32) [a][16]
__device__ __align__(16) uint32_t g_Llo[ATT_ * 16];

// ----------------------------- helpers -------------------------------------
__device__ __forceinline__ uint32_t smem_u32(const void* p) {
    uint32_t a;
    asm("{ .reg .u64 t; cvta.to.shared.u64 t, %1; cvt.u32.u64 %0, t; }"
        : "=r"(a) : "l"(p));
    return a;
}
#define CP_ASYNC16(dst, src) \
    asm volatile("cp.async.cg.shared.global [%0], [%1], 16;" :: "r"(dst), "l"(src))
#define CP_COMMIT() asm volatile("cp.async.commit_group;" ::: "memory")
#define CP_WAIT0()  asm volatile("cp.async.wait_group 0;" ::: "memory")

__device__ __forceinline__ void ldsm4(uint32_t* r, uint32_t addr) {
    asm volatile("ldmatrix.sync.aligned.m8n8.x4.shared.b16 {%0,%1,%2,%3}, [%4];"
                 : "=r"(r[0]), "=r"(r[1]), "=r"(r[2]), "=r"(r[3]) : "r"(addr));
}
__device__ __forceinline__ void hmma(float* c, const uint32_t* a,
                                     const uint32_t* b) {
    asm volatile(
        "mma.sync.aligned.m16n8k16.row.col.f32.f16.f16.f32 "
        "{%0,%1,%2,%3},{%4,%5,%6,%7},{%8,%9},{%0,%1,%2,%3};"
        : "+f"(c[0]), "+f"(c[1]), "+f"(c[2]), "+f"(c[3])
        : "r"(a[0]), "r"(a[1]), "r"(a[2]), "r"(a[3]), "r"(b[0]), "r"(b[1]));
}
__device__ __forceinline__ uint32_t pack_h2(float a, float b) {
    __half2 h = __floats2half2_rn(a, b);
    return *reinterpret_cast<uint32_t*>(&h);
}
// fp16 hi/lo split: hi = rn(x), lo = rn(x - hi)
__device__ __forceinline__ void split_pack_f16(float a, float b,
                                               uint32_t& hi, uint32_t& lo) {
    __half2 h = __floats2half2_rn(a, b);
    float ra = a - __half2float(__low2half(h));
    float rb = b - __half2float(__high2half(h));
    hi = *reinterpret_cast<uint32_t*>(&h);
    lo = pack_h2(ra, rb);
}
__device__ __forceinline__ float tanh_acc(float x) {
    x = fminf(fmaxf(x, -15.f), 15.f);
    float t, r;
    asm("ex2.approx.f32 %0, %1;" : "=f"(t) : "f"(x * 2.8853900817779268f));
    asm("rcp.approx.f32 %0, %1;" : "=f"(r) : "f"(t + 1.f));
    return (t - 1.f) * r;
}

// ---------------------------------------------------------------------------
// fused prep: blocks 0..63 q; 64..191 pack_A; 192..199 pack_L
// ---------------------------------------------------------------------------
__global__ void prep_kernel(const float* __restrict__ query,
                            const float* __restrict__ Qw,
                            const float* __restrict__ Qb,
                            const float* __restrict__ Vw,
                            const float* __restrict__ lp,
                            const float* __restrict__ cw) {
    int bid = blockIdx.x, tid = threadIdx.x;
    if (bid < 64) {                      // q = query @ Qw^T + Qb
        int b = bid, wid = tid >> 5, lane = tid & 31;
        #pragma unroll 1
        for (int ai = 0; ai < 16; ai++) {
            int a = wid * 16 + ai;
            float s = 0.f;
            #pragma unroll 8
            for (int k = lane; k < DEC_; k += 32)
                s += query[b * DEC_ + k] * Qw[a * DEC_ + k];
            #pragma unroll
            for (int o = 16; o > 0; o >>= 1)
                s += __shfl_down_sync(0xffffffffu, s, o);
            if (lane == 0) g_q[b * ATT_ + a] = s + Qb[a];
        }
    } else if (bid < 192) {              // pack Vw -> fp16 hi/lo
        int a = bid - 64;
        float f0 = Vw[a * ENC_ + 2 * tid], f1 = Vw[a * ENC_ + 2 * tid + 1];
        uint32_t hi, lo;
        split_pack_f16(f0, f1, hi, lo);
        g_Ahi[a * 256 + tid] = hi;
        g_Alo[a * 256 + tid] = lo;
    } else {                             // Weff + pack
        int idx = (bid - 192) * 256 + tid;   // 0..2047 = 128*16
        int a = idx >> 4, p = idx & 15;
        int k0 = 2 * p, k1 = k0 + 1;
        float w0 = 0.f, w1 = 0.f;
        #pragma unroll
        for (int c = 0; c < LOC_; c++) {
            float l = lp[a * LOC_ + c];
            w0 += l * cw[c * KW_ + k0];
            if (k1 < KW_) w1 += l * cw[c * KW_ + k1];
        }
        uint32_t hi, lo;
        split_pack_f16(w0, w1, hi, lo);
        g_Lhi[idx] = hi;
        g_Llo[idx] = lo;
    }
}

// ---------------------------------------------------------------------------
// main energies kernel: 512 threads, tile 128a x 128t
// 8 chunks of k=64 + 1 loc chunk of k=32; A (hi+lo) + B (single) dbl buffered
// ---------------------------------------------------------------------------
#define NT     512
#define LDR    144       // smem row stride bytes (64 fp16 data + 16B pad)
#define A_TILE 18432     // 128 rows * 144B
#define OFF_A   0                        // 2 buf x 2 sel x A_TILE = 73728
#define OFF_B   73728                    // 2 buf x A_TILE = 36864
#define OFF_CAW 110592                   // 160 floats
#define OFF_Q   111232                   // 128 floats
#define OFF_VWV 111744                   // 128 floats
#define OFF_RED 112256                   // 512 floats
#define SMEM_MAIN (OFF_RED + 2048)

// KC=64 chunk A loader (c in 0..7): hi+lo images
__device__ __forceinline__ void load_A_async64(uint32_t dstbase, int c, int tid) {
    #pragma unroll
    for (int i = 0; i < 4; i++) {
        int idx = tid + i * NT;           // 0..2047
        int sel = idx >> 10;
        int g = idx & 1023;
        int row = g >> 3, seg = g & 7;
        const uint32_t* src = (sel ? g_Alo : g_Ahi) + row * 256 + c * 32 + seg * 4;
        uint32_t dst = dstbase + sel * A_TILE + row * LDR + seg * 16;
        CP_ASYNC16(dst, src);
    }
}
// loc chunk (k=32) A loader
__device__ __forceinline__ void load_A_asyncL(uint32_t dstbase, int tid) {
    #pragma unroll
    for (int i = 0; i < 2; i++) {
        int idx = tid + i * NT;           // 0..1023
        int sel = idx >> 9;
        int g = idx & 511;
        int row = g >> 2, seg = g & 3;
        const uint32_t* src = (sel ? g_Llo : g_Lhi) + row * 16 + seg * 4;
        uint32_t dst = dstbase + sel * A_TILE + row * LDR + seg * 16;
        CP_ASYNC16(dst, src);
    }
}

__device__ __forceinline__ void load_B_regs64(const float* __restrict__ vb,
                                              int c, int tid, float4* v) {
    #pragma unroll
    for (int j = 0; j < 4; j++) {
        int idx = tid + j * NT;
        int row = idx >> 4, col4 = idx & 15;
        v[j] = *(const float4*)(vb + (size_t)row * ENC_ + c * 64 + col4 * 4);
    }
}
__device__ __forceinline__ void load_B_regsL(const float* __restrict__ caw_s,
                                             int tid, float4* v) {
    #pragma unroll
    for (int j = 0; j < 2; j++) {
        int idx = tid + j * NT;
        int row = idx >> 3, col4 = idx & 7;
        int k0 = col4 * 4;
        v[j].x = (k0 + 0 < KW_) ? caw_s[row + k0 + 0] : 0.f;
        v[j].y = (k0 + 1 < KW_) ? caw_s[row + k0 + 1] : 0.f;
        v[j].z = (k0 + 2 < KW_) ? caw_s[row + k0 + 2] : 0.f;
        v[j].w = (k0 + 3 < KW_) ? caw_s[row + k0 + 3] : 0.f;
    }
}

// B store: single fp16 image
__device__ __forceinline__ void store_B64(char* smem, uint32_t bufoff, int tid,
                                          const float4* v) {
    #pragma unroll
    for (int j = 0; j < 4; j++) {
        int idx = tid + j * NT;
        int row = idx >> 4, col4 = idx & 15;
        uint32_t p01 = pack_h2(v[j].x, v[j].y);
        uint32_t p23 = pack_h2(v[j].z, v[j].w);
        *(uint2*)(smem + OFF_B + bufoff + row * LDR + col4 * 8) =
            make_uint2(p01, p23);
    }
}
__device__ __forceinline__ void store_BL(char* smem, uint32_t bufoff, int tid,
                                         const float4* v) {
    #pragma unroll
    for (int j = 0; j < 2; j++) {
        int idx = tid + j * NT;
        int row = idx >> 3, col4 = idx & 7;
        uint32_t p01 = pack_h2(v[j].x, v[j].y);
        uint32_t p23 = pack_h2(v[j].z, v[j].w);
        *(uint2*)(smem + OFF_B + bufoff + row * LDR + col4 * 8) =
            make_uint2(p01, p23);
    }
}

template <int NK16>
__device__ __forceinline__ void compute_chunk(float (&acc)[2][4][4], uint32_t sb,
                                              int buf, int wm, int wn, int lane) {
    const uint32_t smA = sb + OFF_A + buf * 2 * A_TILE;
    const uint32_t smB = sb + OFF_B + buf * A_TILE;
    #pragma unroll
    for (int k16 = 0; k16 < NK16; k16++) {
        const int colb = k16 * 32;
        uint32_t ahi[2][4], alo[2][4];
        #pragma unroll
        for (int mt = 0; mt < 2; mt++) {
            uint32_t ad = smA + (wm + mt * 16 + (lane & 15)) * LDR + colb +
                          ((lane >> 4) << 4);
            ldsm4(ahi[mt], ad);
            ldsm4(alo[mt], ad + A_TILE);
        }
        uint32_t bfr[2][4];
        #pragma unroll
        for (int np = 0; np < 2; np++) {
            int grp = lane >> 3;
            uint32_t bd = smB + (wn + np * 16 + (grp >> 1) * 8 + (lane & 7)) * LDR +
                          colb + ((grp & 1) << 4);
            ldsm4(bfr[np], bd);
        }
        #pragma unroll
        for (int mt = 0; mt < 2; mt++)
            #pragma unroll
            for (int nt = 0; nt < 4; nt++) {
                const uint32_t* bp = &bfr[nt >> 1][(nt & 1) * 2];
                hmma(acc[mt][nt], ahi[mt], bp);
                hmma(acc[mt][nt], alo[mt], bp);
            }
    }
}

__global__ __launch_bounds__(NT, 1)
void main_mma(const float* __restrict__ values,
              const float* __restrict__ caw,
              const float* __restrict__ vw_vec) {
    extern __shared__ __align__(16) char smem[];
    const uint32_t sb = smem_u32(smem);
    const int tid = threadIdx.x, wid = tid >> 5, lane = tid & 31;
    const int b = blockIdx.y, t0 = blockIdx.x * 128;
    const int wm = (wid & 3) * 32, wn = (wid >> 2) * 32;

    float* caw_s = (float*)(smem + OFF_CAW);
    float* q_s   = (float*)(smem + OFF_Q);
    float* vwv_s = (float*)(smem + OFF_VWV);
    float* red_s = (float*)(smem + OFF_RED);

    if (tid < 160) {
        int gt = t0 - 15 + tid;
        caw_s[tid] = (gt >= 0 && gt < T_) ? caw[b * T_ + gt] : 0.f;
    }
    if (tid < ATT_) {
        q_s[tid]   = g_q[b * ATT_ + tid];
        vwv_s[tid] = vw_vec[tid];
    }
    __syncthreads();

    const float* vb = values + (size_t)(b * T_ + t0) * ENC_;
    float acc[2][4][4];
    #pragma unroll
    for (int i = 0; i < 2; i++)
        #pragma unroll
        for (int j = 0; j < 4; j++)
            #pragma unroll
            for (int e = 0; e < 4; e++) acc[i][j][e] = 0.f;

    float4 v[4];
    // prologue: chunk 0
    load_A_async64(sb + OFF_A, 0, tid);
    CP_COMMIT();
    load_B_regs64(vb, 0, tid, v);
    store_B64(smem, 0, tid, v);
    CP_WAIT0();
    __syncthreads();

    #pragma unroll 1
    for (int c = 0; c < 8; c++) {
        const int nb = c + 1;
        if (nb < 8) {
            load_A_async64(sb + OFF_A + (nb & 1) * 2 * A_TILE, nb, tid);
            CP_COMMIT();
            load_B_regs64(vb, nb, tid, v);
        } else {
            load_A_asyncL(sb + OFF_A + (nb & 1) * 2 * A_TILE, tid);   // buf 0
            CP_COMMIT();
            load_B_regsL(caw_s, tid, v);
        }
        compute_chunk<4>(acc, sb, c & 1, wm, wn, lane);
        if (nb < 8) store_B64(smem, (nb & 1) * A_TILE, tid, v);
        else        store_BL(smem, (nb & 1) * A_TILE, tid, v);        // buf 0
        CP_WAIT0();
        __syncthreads();
    }
    // loc chunk lives in buffer 0 ((8&1)==0) — FIX: was buf 1 in round 6
    compute_chunk<2>(acc, sb, 0, wm, wn, lane);

    // epilogue: tanh + weighted reduce over a
    float part[4][2];
    #pragma unroll
    for (int nt = 0; nt < 4; nt++) { part[nt][0] = 0.f; part[nt][1] = 0.f; }
    const int r0 = lane >> 2;
    #pragma unroll
    for (int mt = 0; mt < 2; mt++) {
        #pragma unroll
        for (int half = 0; half < 2; half++) {
            int a = wm + mt * 16 + r0 + half * 8;
            float qa = q_s[a], va = vwv_s[a];
            #pragma unroll
            for (int nt = 0; nt < 4; nt++) {
                #pragma unroll
                for (int p = 0; p < 2; p++) {
                    float x = acc[mt][nt][half * 2 + p] + qa;
                    part[nt][p] += va * tanh_acc(x);
                }
            }
        }
    }
    #pragma unroll
    for (int off = 4; off < 32; off <<= 1)
        #pragma unroll
        for (int nt = 0; nt < 4; nt++) {
            part[nt][0] += __shfl_xor_sync(0xffffffffu, part[nt][0], off);
            part[nt][1] += __shfl_xor_sync(0xffffffffu, part[nt][1], off);
        }
    if (lane < 4) {
        #pragma unroll
        for (int nt = 0; nt < 4; nt++) {
            red_s[(wid & 3) * 128 + wn + nt * 8 + lane * 2 + 0] = part[nt][0];
            red_s[(wid & 3) * 128 + wn + nt * 8 + lane * 2 + 1] = part[nt][1];
        }
    }
    __syncthreads();
    if (tid < 128)
        g_energies[b * T_ + t0 + tid] = (red_s[tid] + red_s[128 + tid]) +
                                        (red_s[256 + tid] + red_s[384 + tid]);
}

// ---------------------------------------------------------------------------
// masked softmax over T per b
// ---------------------------------------------------------------------------
__global__ void softmax_kernel(const unsigned char* __restrict__ maskb,
                               float* __restrict__ out_w) {
    __shared__ float red[256];
    int b = blockIdx.x, tid = threadIdx.x;
    float e[8];
    float mx = -3.402823466e38f;
    #pragma unroll
    for (int i = 0; i < 8; i++) {
        int t = tid + i * 256;
        float v = g_energies[b * T_ + t];
        if (maskb[b * T_ + t]) v = __int_as_float(0xff800000);
        e[i] = v;
        mx = fmaxf(mx, v);
    }
    red[tid] = mx;
    __syncthreads();
    for (int s = 128; s > 0; s >>= 1) {
        if (tid < s) red[tid] = fmaxf(red[tid], red[tid + s]);
        __syncthreads();
    }
    mx = red[0];
    __syncthreads();
    float sum = 0.f;
    #pragma unroll
    for (int i = 0; i < 8; i++) {
        e[i] = expf(e[i] - mx);
        sum += e[i];
    }
    red[tid] = sum;
    __syncthreads();
    for (int s = 128; s > 0; s >>= 1) {
        if (tid < s) red[tid] += red[tid + s];
        __syncthreads();
    }
    float inv = 1.f / red[0];
    #pragma unroll
    for (int i = 0; i < 8; i++)
        out_w[b * T_ + tid + i * 256] = e[i] * inv;
}

// ---------------------------------------------------------------------------
// context = weights @ values : float4 loads, 16 t-chunks of 128, parity pairs
// ---------------------------------------------------------------------------
__global__ void ctx_partial(const float* __restrict__ values,
                            const float* __restrict__ w) {
    __shared__ float sw[128];
    __shared__ float4 sh[128];
    int b = blockIdx.y, ch = blockIdx.x, tid = threadIdx.x;  // 256 threads
    int col4 = tid & 127, parity = tid >> 7;
    const float* vb = values + (size_t)(b * T_ + ch * 128) * ENC_;
    if (tid < 128) sw[tid] = w[b * T_ + ch * 128 + tid];
    __syncthreads();
    float4 acc = make_float4(0.f, 0.f, 0.f, 0.f);
    #pragma unroll 4
    for (int r = parity; r < 128; r += 2) {
        float wt = sw[r];
        float4 vv = *(const float4*)(vb + (size_t)r * ENC_ + col4 * 4);
        acc.x += wt * vv.x;
        acc.y += wt * vv.y;
        acc.z += wt * vv.z;
        acc.w += wt * vv.w;
    }
    if (parity == 1) sh[col4] = acc;
    __syncthreads();
    if (parity == 0) {
        float4 o = sh[col4];
        o.x += acc.x; o.y += acc.y; o.z += acc.z; o.w += acc.w;
        *(float4*)(&g_ctx_part[(size_t)(b * 16 + ch) * ENC_ + col4 * 4]) = o;
    }
}

__global__ void ctx_reduce(float* __restrict__ out_ctx) {
    int idx = blockIdx.x * 256 + threadIdx.x;
    int b = idx >> 9, c = idx & 511;
    float s = 0.f;
    #pragma unroll
    for (int ch = 0; ch < 16; ch++)
        s += g_ctx_part[(size_t)(b * 16 + ch) * ENC_ + c];
    out_ctx[idx] = s;
}

// ---------------------------------------------------------------------------
extern "C" void kernel_launch(void* const* d_in, const int* in_sizes, int n_in,
                              void* d_out, int out_size) {
    const float* query = (const float*)d_in[0];
    const float* values = (const float*)d_in[1];
    const float* caw   = (const float*)d_in[2];
    const unsigned char* mask = (const unsigned char*)d_in[3];
    const float* Qw    = (const float*)d_in[4];
    const float* Qb    = (const float*)d_in[5];
    const float* Vw    = (const float*)d_in[6];
    const float* convw = (const float*)d_in[7];
    const float* locp  = (const float*)d_in[8];
    const float* vw    = (const float*)d_in[9];

    float* out_ctx = (float*)d_out;              // [B, ENC]
    float* out_w   = (float*)d_out + B_ * ENC_;  // [B, T]

    cudaFuncSetAttribute(main_mma,
                         cudaFuncAttributeMaxDynamicSharedMemorySize, SMEM_MAIN);

    prep_kernel<<<200, 256>>>(query, Qw, Qb, Vw, locp, convw);
    main_mma<<<dim3(T_ / 128, B_), NT, SMEM_MAIN>>>(values, caw, vw);
    softmax_kernel<<<B_, 256>>>(mask, out_w);
    ctx_partial<<<dim3(16, B_), 256>>>(values, out_w);
    ctx_reduce<<<(B_ * ENC_) / 256, 256>>>(out_ctx);
}

// round 8
// speedup vs baseline: 4.0448x; 1.0111x over previous
#include <cuda_runtime.h>
#include <cuda_fp16.h>
#include <cstdint>

// ---------------------------------------------------------------------------
// LocalSensitiveAttention on GB300 (sm_103 baseline ptx: legacy HMMA mma.sync)
// energies = vw . tanh(Vw@values^T + Weff@cawband^T + q); softmax; ctx.
// Round 8: main_mma writes its fp16 values conversion to g_vh; ctx_partial
// reads fp16 (128MB instead of 256MB) -> ctx roofline time halves.
// A (weights) = fp16 hi+lo (err ~2^-22), B (values) = single fp16 (err 2^-11).
// ---------------------------------------------------------------------------

#define B_    64
#define T_    2048
#define DEC_  1024
#define ENC_  512
#define ATT_  128
#define LOC_  32
#define KW_   31

__device__ float g_q[B_ * ATT_];
__device__ float g_energies[B_ * T_];
__device__ float g_ctx_part[B_ * 16 * ENC_];
__device__ __align__(16) uint32_t g_Ahi[ATT_ * 256];  // Vw hi fp16 pairs [a][256]
__device__ __align__(16) uint32_t g_Alo[ATT_ * 256];
__device__ __align__(16) uint32_t g_Lhi[ATT_ * 16];   // Weff (pad k32) [a][16]
__device__ __align__(16) uint32_t g_Llo[ATT_ * 16];
// fp16 image of values, written by main_mma, read by ctx_partial (134MB)
__device__ __align__(16) __half2 g_vh[(size_t)B_ * T_ * ENC_ / 2];

// ----------------------------- helpers -------------------------------------
__device__ __forceinline__ uint32_t smem_u32(const void* p) {
    uint32_t a;
    asm("{ .reg .u64 t; cvta.to.shared.u64 t, %1; cvt.u32.u64 %0, t; }"
        : "=r"(a) : "l"(p));
    return a;
}
#define CP_ASYNC16(dst, src) \
    asm volatile("cp.async.cg.shared.global [%0], [%1], 16;" :: "r"(dst), "l"(src))
#define CP_COMMIT() asm volatile("cp.async.commit_group;" ::: "memory")
#define CP_WAIT0()  asm volatile("cp.async.wait_group 0;" ::: "memory")

__device__ __forceinline__ void ldsm4(uint32_t* r, uint32_t addr) {
    asm volatile("ldmatrix.sync.aligned.m8n8.x4.shared.b16 {%0,%1,%2,%3}, [%4];"
                 : "=r"(r[0]), "=r"(r[1]), "=r"(r[2]), "=r"(r[3]) : "r"(addr));
}
__device__ __forceinline__ void hmma(float* c, const uint32_t* a,
                                     const uint32_t* b) {
    asm volatile(
        "mma.sync.aligned.m16n8k16.row.col.f32.f16.f16.f32 "
        "{%0,%1,%2,%3},{%4,%5,%6,%7},{%8,%9},{%0,%1,%2,%3};"
        : "+f"(c[0]), "+f"(c[1]), "+f"(c[2]), "+f"(c[3])
        : "r"(a[0]), "r"(a[1]), "r"(a[2]), "r"(a[3]), "r"(b[0]), "r"(b[1]));
}
__device__ __forceinline__ uint32_t pack_h2(float a, float b) {
    __half2 h = __floats2half2_rn(a, b);
    return *reinterpret_cast<uint32_t*>(&h);
}
// fp16 hi/lo split: hi = rn(x), lo = rn(x - hi)
__device__ __forceinline__ void split_pack_f16(float a, float b,
                                               uint32_t& hi, uint32_t& lo) {
    __half2 h = __floats2half2_rn(a, b);
    float ra = a - __half2float(__low2half(h));
    float rb = b - __half2float(__high2half(h));
    hi = *reinterpret_cast<uint32_t*>(&h);
    lo = pack_h2(ra, rb);
}
__device__ __forceinline__ float tanh_acc(float x) {
    x = fminf(fmaxf(x, -15.f), 15.f);
    float t, r;
    asm("ex2.approx.f32 %0, %1;" : "=f"(t) : "f"(x * 2.8853900817779268f));
    asm("rcp.approx.f32 %0, %1;" : "=f"(r) : "f"(t + 1.f));
    return (t - 1.f) * r;
}

// ---------------------------------------------------------------------------
// fused prep: blocks 0..63 q; 64..191 pack_A; 192..199 pack_L
// ---------------------------------------------------------------------------
__global__ void prep_kernel(const float* __restrict__ query,
                            const float* __restrict__ Qw,
                            const float* __restrict__ Qb,
                            const float* __restrict__ Vw,
                            const float* __restrict__ lp,
                            const float* __restrict__ cw) {
    int bid = blockIdx.x, tid = threadIdx.x;
    if (bid < 64) {                      // q = query @ Qw^T + Qb
        int b = bid, wid = tid >> 5, lane = tid & 31;
        #pragma unroll 1
        for (int ai = 0; ai < 16; ai++) {
            int a = wid * 16 + ai;
            float s = 0.f;
            #pragma unroll 8
            for (int k = lane; k < DEC_; k += 32)
                s += query[b * DEC_ + k] * Qw[a * DEC_ + k];
            #pragma unroll
            for (int o = 16; o > 0; o >>= 1)
                s += __shfl_down_sync(0xffffffffu, s, o);
            if (lane == 0) g_q[b * ATT_ + a] = s + Qb[a];
        }
    } else if (bid < 192) {              // pack Vw -> fp16 hi/lo
        int a = bid - 64;
        float f0 = Vw[a * ENC_ + 2 * tid], f1 = Vw[a * ENC_ + 2 * tid + 1];
        uint32_t hi, lo;
        split_pack_f16(f0, f1, hi, lo);
        g_Ahi[a * 256 + tid] = hi;
        g_Alo[a * 256 + tid] = lo;
    } else {                             // Weff + pack
        int idx = (bid - 192) * 256 + tid;   // 0..2047 = 128*16
        int a = idx >> 4, p = idx & 15;
        int k0 = 2 * p, k1 = k0 + 1;
        float w0 = 0.f, w1 = 0.f;
        #pragma unroll
        for (int c = 0; c < LOC_; c++) {
            float l = lp[a * LOC_ + c];
            w0 += l * cw[c * KW_ + k0];
            if (k1 < KW_) w1 += l * cw[c * KW_ + k1];
        }
        uint32_t hi, lo;
        split_pack_f16(w0, w1, hi, lo);
        g_Lhi[idx] = hi;
        g_Llo[idx] = lo;
    }
}

// ---------------------------------------------------------------------------
// main energies kernel: 512 threads, tile 128a x 128t
// 8 chunks of k=64 + 1 loc chunk of k=32; A (hi+lo) + B (single) dbl buffered
// ---------------------------------------------------------------------------
#define NT     512
#define LDR    144       // smem row stride bytes (64 fp16 data + 16B pad)
#define A_TILE 18432     // 128 rows * 144B
#define OFF_A   0                        // 2 buf x 2 sel x A_TILE = 73728
#define OFF_B   73728                    // 2 buf x A_TILE = 36864
#define OFF_CAW 110592                   // 160 floats
#define OFF_Q   111232                   // 128 floats
#define OFF_VWV 111744                   // 128 floats
#define OFF_RED 112256                   // 512 floats
#define SMEM_MAIN (OFF_RED + 2048)

// KC=64 chunk A loader (c in 0..7): hi+lo images
__device__ __forceinline__ void load_A_async64(uint32_t dstbase, int c, int tid) {
    #pragma unroll
    for (int i = 0; i < 4; i++) {
        int idx = tid + i * NT;           // 0..2047
        int sel = idx >> 10;
        int g = idx & 1023;
        int row = g >> 3, seg = g & 7;
        const uint32_t* src = (sel ? g_Alo : g_Ahi) + row * 256 + c * 32 + seg * 4;
        uint32_t dst = dstbase + sel * A_TILE + row * LDR + seg * 16;
        CP_ASYNC16(dst, src);
    }
}
// loc chunk (k=32) A loader
__device__ __forceinline__ void load_A_asyncL(uint32_t dstbase, int tid) {
    #pragma unroll
    for (int i = 0; i < 2; i++) {
        int idx = tid + i * NT;           // 0..1023
        int sel = idx >> 9;
        int g = idx & 511;
        int row = g >> 2, seg = g & 3;
        const uint32_t* src = (sel ? g_Llo : g_Lhi) + row * 16 + seg * 4;
        uint32_t dst = dstbase + sel * A_TILE + row * LDR + seg * 16;
        CP_ASYNC16(dst, src);
    }
}

__device__ __forceinline__ void load_B_regs64(const float* __restrict__ vb,
                                              int c, int tid, float4* v) {
    #pragma unroll
    for (int j = 0; j < 4; j++) {
        int idx = tid + j * NT;
        int row = idx >> 4, col4 = idx & 15;
        v[j] = *(const float4*)(vb + (size_t)row * ENC_ + c * 64 + col4 * 4);
    }
}
__device__ __forceinline__ void load_B_regsL(const float* __restrict__ caw_s,
                                             int tid, float4* v) {
    #pragma unroll
    for (int j = 0; j < 2; j++) {
        int idx = tid + j * NT;
        int row = idx >> 3, col4 = idx & 7;
        int k0 = col4 * 4;
        v[j].x = (k0 + 0 < KW_) ? caw_s[row + k0 + 0] : 0.f;
        v[j].y = (k0 + 1 < KW_) ? caw_s[row + k0 + 1] : 0.f;
        v[j].z = (k0 + 2 < KW_) ? caw_s[row + k0 + 2] : 0.f;
        v[j].w = (k0 + 3 < KW_) ? caw_s[row + k0 + 3] : 0.f;
    }
}

// B store: single fp16 image to smem + byproduct STG of fp16 values to g_vh
__device__ __forceinline__ void store_B64(char* smem, uint32_t bufoff, int tid,
                                          const float4* v, __half2* vhb, int c) {
    #pragma unroll
    for (int j = 0; j < 4; j++) {
        int idx = tid + j * NT;
        int row = idx >> 4, col4 = idx & 15;
        uint32_t p01 = pack_h2(v[j].x, v[j].y);
        uint32_t p23 = pack_h2(v[j].z, v[j].w);
        *(uint2*)(smem + OFF_B + bufoff + row * LDR + col4 * 8) =
            make_uint2(p01, p23);
        // global fp16 image for ctx pass: [row][ENC] halves => half2 stride 256
        *(uint2*)(vhb + (size_t)row * 256 + c * 32 + col4 * 2) =
            make_uint2(p01, p23);
    }
}
__device__ __forceinline__ void store_BL(char* smem, uint32_t bufoff, int tid,
                                         const float4* v) {
    #pragma unroll
    for (int j = 0; j < 2; j++) {
        int idx = tid + j * NT;
        int row = idx >> 3, col4 = idx & 7;
        uint32_t p01 = pack_h2(v[j].x, v[j].y);
        uint32_t p23 = pack_h2(v[j].z, v[j].w);
        *(uint2*)(smem + OFF_B + bufoff + row * LDR + col4 * 8) =
            make_uint2(p01, p23);
    }
}

template <int NK16>
__device__ __forceinline__ void compute_chunk(float (&acc)[2][4][4], uint32_t sb,
                                              int buf, int wm, int wn, int lane) {
    const uint32_t smA = sb + OFF_A + buf * 2 * A_TILE;
    const uint32_t smB = sb + OFF_B + buf * A_TILE;
    #pragma unroll
    for (int k16 = 0; k16 < NK16; k16++) {
        const int colb = k16 * 32;
        uint32_t ahi[2][4], alo[2][4];
        #pragma unroll
        for (int mt = 0; mt < 2; mt++) {
            uint32_t ad = smA + (wm + mt * 16 + (lane & 15)) * LDR + colb +
                          ((lane >> 4) << 4);
            ldsm4(ahi[mt], ad);
            ldsm4(alo[mt], ad + A_TILE);
        }
        uint32_t bfr[2][4];
        #pragma unroll
        for (int np = 0; np < 2; np++) {
            int grp = lane >> 3;
            uint32_t bd = smB + (wn + np * 16 + (grp >> 1) * 8 + (lane & 7)) * LDR +
                          colb + ((grp & 1) << 4);
            ldsm4(bfr[np], bd);
        }
        #pragma unroll
        for (int mt = 0; mt < 2; mt++)
            #pragma unroll
            for (int nt = 0; nt < 4; nt++) {
                const uint32_t* bp = &bfr[nt >> 1][(nt & 1) * 2];
                hmma(acc[mt][nt], ahi[mt], bp);
                hmma(acc[mt][nt], alo[mt], bp);
            }
    }
}

__global__ __launch_bounds__(NT, 1)
void main_mma(const float* __restrict__ values,
              const float* __restrict__ caw,
              const float* __restrict__ vw_vec) {
    extern __shared__ __align__(16) char smem[];
    const uint32_t sb = smem_u32(smem);
    const int tid = threadIdx.x, wid = tid >> 5, lane = tid & 31;
    const int b = blockIdx.y, t0 = blockIdx.x * 128;
    const int wm = (wid & 3) * 32, wn = (wid >> 2) * 32;

    float* caw_s = (float*)(smem + OFF_CAW);
    float* q_s   = (float*)(smem + OFF_Q);
    float* vwv_s = (float*)(smem + OFF_VWV);
    float* red_s = (float*)(smem + OFF_RED);

    if (tid < 160) {
        int gt = t0 - 15 + tid;
        caw_s[tid] = (gt >= 0 && gt < T_) ? caw[b * T_ + gt] : 0.f;
    }
    if (tid < ATT_) {
        q_s[tid]   = g_q[b * ATT_ + tid];
        vwv_s[tid] = vw_vec[tid];
    }
    __syncthreads();

    const float* vb = values + (size_t)(b * T_ + t0) * ENC_;
    __half2* vhb = g_vh + (size_t)(b * T_ + t0) * (ENC_ / 2);
    float acc[2][4][4];
    #pragma unroll
    for (int i = 0; i < 2; i++)
        #pragma unroll
        for (int j = 0; j < 4; j++)
            #pragma unroll
            for (int e = 0; e < 4; e++) acc[i][j][e] = 0.f;

    float4 v[4];
    // prologue: chunk 0
    load_A_async64(sb + OFF_A, 0, tid);
    CP_COMMIT();
    load_B_regs64(vb, 0, tid, v);
    store_B64(smem, 0, tid, v, vhb, 0);
    CP_WAIT0();
    __syncthreads();

    #pragma unroll 1
    for (int c = 0; c < 8; c++) {
        const int nb = c + 1;
        if (nb < 8) {
            load_A_async64(sb + OFF_A + (nb & 1) * 2 * A_TILE, nb, tid);
            CP_COMMIT();
            load_B_regs64(vb, nb, tid, v);
        } else {
            load_A_asyncL(sb + OFF_A + (nb & 1) * 2 * A_TILE, tid);   // buf 0
            CP_COMMIT();
            load_B_regsL(caw_s, tid, v);
        }
        compute_chunk<4>(acc, sb, c & 1, wm, wn, lane);
        if (nb < 8) store_B64(smem, (nb & 1) * A_TILE, tid, v, vhb, nb);
        else        store_BL(smem, (nb & 1) * A_TILE, tid, v);        // buf 0
        CP_WAIT0();
        __syncthreads();
    }
    // loc chunk lives in buffer 0 ((8&1)==0)
    compute_chunk<2>(acc, sb, 0, wm, wn, lane);

    // epilogue: tanh + weighted reduce over a
    float part[4][2];
    #pragma unroll
    for (int nt = 0; nt < 4; nt++) { part[nt][0] = 0.f; part[nt][1] = 0.f; }
    const int r0 = lane >> 2;
    #pragma unroll
    for (int mt = 0; mt < 2; mt++) {
        #pragma unroll
        for (int half = 0; half < 2; half++) {
            int a = wm + mt * 16 + r0 + half * 8;
            float qa = q_s[a], va = vwv_s[a];
            #pragma unroll
            for (int nt = 0; nt < 4; nt++) {
                #pragma unroll
                for (int p = 0; p < 2; p++) {
                    float x = acc[mt][nt][half * 2 + p] + qa;
                    part[nt][p] += va * tanh_acc(x);
                }
            }
        }
    }
    #pragma unroll
    for (int off = 4; off < 32; off <<= 1)
        #pragma unroll
        for (int nt = 0; nt < 4; nt++) {
            part[nt][0] += __shfl_xor_sync(0xffffffffu, part[nt][0], off);
            part[nt][1] += __shfl_xor_sync(0xffffffffu, part[nt][1], off);
        }
    if (lane < 4) {
        #pragma unroll
        for (int nt = 0; nt < 4; nt++) {
            red_s[(wid & 3) * 128 + wn + nt * 8 + lane * 2 + 0] = part[nt][0];
            red_s[(wid & 3) * 128 + wn + nt * 8 + lane * 2 + 1] = part[nt][1];
        }
    }
    __syncthreads();
    if (tid < 128)
        g_energies[b * T_ + t0 + tid] = (red_s[tid] + red_s[128 + tid]) +
                                        (red_s[256 + tid] + red_s[384 + tid]);
}

// ---------------------------------------------------------------------------
// masked softmax over T per b
// ---------------------------------------------------------------------------
__global__ void softmax_kernel(const unsigned char* __restrict__ maskb,
                               float* __restrict__ out_w) {
    __shared__ float red[256];
    int b = blockIdx.x, tid = threadIdx.x;
    float e[8];
    float mx = -3.402823466e38f;
    #pragma unroll
    for (int i = 0; i < 8; i++) {
        int t = tid + i * 256;
        float v = g_energies[b * T_ + t];
        if (maskb[b * T_ + t]) v = __int_as_float(0xff800000);
        e[i] = v;
        mx = fmaxf(mx, v);
    }
    red[tid] = mx;
    __syncthreads();
    for (int s = 128; s > 0; s >>= 1) {
        if (tid < s) red[tid] = fmaxf(red[tid], red[tid + s]);
        __syncthreads();
    }
    mx = red[0];
    __syncthreads();
    float sum = 0.f;
    #pragma unroll
    for (int i = 0; i < 8; i++) {
        e[i] = expf(e[i] - mx);
        sum += e[i];
    }
    red[tid] = sum;
    __syncthreads();
    for (int s = 128; s > 0; s >>= 1) {
        if (tid < s) red[tid] += red[tid + s];
        __syncthreads();
    }
    float inv = 1.f / red[0];
    #pragma unroll
    for (int i = 0; i < 8; i++)
        out_w[b * T_ + tid + i * 256] = e[i] * inv;
}

// ---------------------------------------------------------------------------
// context = weights @ values(fp16 image): uint4 loads of 8 halves per thread
// ---------------------------------------------------------------------------
__global__ void ctx_partial(const float* __restrict__ w) {
    __shared__ float sw[128];
    __shared__ float sh[3][64][8];
    int b = blockIdx.y, ch = blockIdx.x, tid = threadIdx.x;  // 256 threads
    int col8 = tid & 63, parity = tid >> 6;                  // 0..3
    const __half2* vb = g_vh + (size_t)(b * T_ + ch * 128) * (ENC_ / 2);
    if (tid < 128) sw[tid] = w[b * T_ + ch * 128 + tid];
    __syncthreads();
    float acc[8];
    #pragma unroll
    for (int k = 0; k < 8; k++) acc[k] = 0.f;
    #pragma unroll 4
    for (int r = parity; r < 128; r += 4) {
        float wt = sw[r];
        uint4 raw = *(const uint4*)(vb + (size_t)r * (ENC_ / 2) + col8 * 4);
        const __half2* h = (const __half2*)&raw;
        #pragma unroll
        for (int k = 0; k < 4; k++) {
            float2 f = __half22float2(h[k]);
            acc[2 * k + 0] += wt * f.x;
            acc[2 * k + 1] += wt * f.y;
        }
    }
    if (parity > 0) {
        #pragma unroll
        for (int k = 0; k < 8; k++) sh[parity - 1][col8][k] = acc[k];
    }
    __syncthreads();
    if (parity == 0) {
        #pragma unroll
        for (int k = 0; k < 8; k++)
            acc[k] += sh[0][col8][k] + sh[1][col8][k] + sh[2][col8][k];
        float4* dst = (float4*)&g_ctx_part[(size_t)(b * 16 + ch) * ENC_ + col8 * 8];
        dst[0] = make_float4(acc[0], acc[1], acc[2], acc[3]);
        dst[1] = make_float4(acc[4], acc[5], acc[6], acc[7]);
    }
}

__global__ void ctx_reduce(float* __restrict__ out_ctx) {
    int idx = blockIdx.x * 256 + threadIdx.x;
    int b = idx >> 9, c = idx & 511;
    float s = 0.f;
    #pragma unroll
    for (int ch = 0; ch < 16; ch++)
        s += g_ctx_part[(size_t)(b * 16 + ch) * ENC_ + c];
    out_ctx[idx] = s;
}

// ---------------------------------------------------------------------------
extern "C" void kernel_launch(void* const* d_in, const int* in_sizes, int n_in,
                              void* d_out, int out_size) {
    const float* query = (const float*)d_in[0];
    const float* values = (const float*)d_in[1];
    const float* caw   = (const float*)d_in[2];
    const unsigned char* mask = (const unsigned char*)d_in[3];
    const float* Qw    = (const float*)d_in[4];
    const float* Qb    = (const float*)d_in[5];
    const float* Vw    = (const float*)d_in[6];
    const float* convw = (const float*)d_in[7];
    const float* locp  = (const float*)d_in[8];
    const float* vw    = (const float*)d_in[9];

    float* out_ctx = (float*)d_out;              // [B, ENC]
    float* out_w   = (float*)d_out + B_ * ENC_;  // [B, T]

    cudaFuncSetAttribute(main_mma,
                         cudaFuncAttributeMaxDynamicSharedMemorySize, SMEM_MAIN);

    prep_kernel<<<200, 256>>>(query, Qw, Qb, Vw, locp, convw);
    main_mma<<<dim3(T_ / 128, B_), NT, SMEM_MAIN>>>(values, caw, vw);
    softmax_kernel<<<B_, 256>>>(mask, out_w);
    ctx_partial<<<dim3(16, B_), 256>>>(out_w);
    ctx_reduce<<<(B_ * ENC_) / 256, 256>>>(out_ctx);
}